// round 1
// baseline (speedup 1.0000x reference)
#include <cuda_runtime.h>

#define TPB 256
#define TILE 32
#define KE 129   // 2*64+1

#define NMAX 50048
__device__ float g_sum_t[NMAX * 3];
__device__ float g_cnt[NMAX];
__device__ float g_agg_h[NMAX * 64];

// ---------------------------------------------------------------------------
// Zero the scatter accumulators
// ---------------------------------------------------------------------------
__global__ void zero_kernel(int n) {
    long total = (long)n * 68;  // 64 agg_h + 3 sum_t + 1 cnt per node
    long stride = (long)gridDim.x * blockDim.x;
    for (long i = (long)blockIdx.x * blockDim.x + threadIdx.x; i < total; i += stride) {
        long n64 = (long)n * 64;
        long n67 = (long)n * 67;
        if (i < n64)       g_agg_h[i] = 0.f;
        else if (i < n67)  g_sum_t[i - n64] = 0.f;
        else               g_cnt[i - n67] = 0.f;
    }
}

// ---------------------------------------------------------------------------
// Edge kernel: per-edge MLPs + gate + scatter atomics
// smem floats: We1 8256 | We2 4096 | Wc1 4096 | Wc2 64 | biases 192
//              | Ein 32*132 | Hid 32*68 | Diff 96 | row/col 64
// = 23264 floats = 93056 bytes
// ---------------------------------------------------------------------------
__global__ __launch_bounds__(TPB, 2) void edge_kernel(
    const float* __restrict__ h, const float* __restrict__ coord,
    const int* __restrict__ eidx, int E,
    const float* __restrict__ We1, const float* __restrict__ be1,
    const float* __restrict__ We2, const float* __restrict__ be2,
    const float* __restrict__ Wc1, const float* __restrict__ bc1,
    const float* __restrict__ Wc2, const float* __restrict__ bc2)
{
    extern __shared__ float sm[];
    float* sWe1 = sm;                       // 129*64
    float* sWe2 = sWe1 + KE * 64;           // 64*64
    float* sWc1 = sWe2 + 64 * 64;           // 64*64
    float* sWc2 = sWc1 + 64 * 64;           // 64
    float* sB   = sWc2 + 64;                // be1(64) be2(64) bc1(64)
    float* sEin = sB + 192;                 // 32*132 (e_in, later edge_feat)
    float* sHid = sEin + TILE * 132;        // 32*68
    float* sDiff = sHid + TILE * 68;        // 32*3
    int*   sRow = (int*)(sDiff + 96);       // 32
    int*   sCol = sRow + TILE;              // 32

    const int tid = threadIdx.x;

    for (int i = tid; i < KE * 64; i += TPB) sWe1[i] = We1[i];
    for (int i = tid; i < 64 * 64; i += TPB) sWe2[i] = We2[i];
    for (int i = tid; i < 64 * 64; i += TPB) sWc1[i] = Wc1[i];
    if (tid < 64) sWc2[tid] = Wc2[tid];
    if (tid < 64)                 sB[tid]       = be1[tid];
    else if (tid < 128)           sB[tid]       = be2[tid - 64];
    else if (tid < 192)           sB[tid]       = bc1[tid - 128];
    const float bc2v = bc2[0];

    const int el = tid >> 3;     // edge slot within tile (0..31)
    const int jg = tid & 7;      // hidden-slice index (0..7)
    const int j0 = jg * 8;

    const int ntiles = (E + TILE - 1) / TILE;
    for (int t = blockIdx.x; t < ntiles; t += gridDim.x) {
        const int ebase = t * TILE;
        __syncthreads();   // protect smem reuse across tiles

        // --- indices, coord diff, radial ---
        if (tid < TILE) {
            int e = ebase + tid;
            int r = -1, c = 0;
            float rad = 0.f;
            if (e < E) {
                r = eidx[e];
                c = eidx[E + e];
                float dx = coord[r * 3 + 0] - coord[c * 3 + 0];
                float dy = coord[r * 3 + 1] - coord[c * 3 + 1];
                float dz = coord[r * 3 + 2] - coord[c * 3 + 2];
                sDiff[tid * 3 + 0] = dx;
                sDiff[tid * 3 + 1] = dy;
                sDiff[tid * 3 + 2] = dz;
                rad = dx * dx + dy * dy + dz * dz;
            }
            sRow[tid] = r;
            sCol[tid] = c;
            sEin[tid * 132 + 128] = rad;
        }
        __syncthreads();

        // --- gather h[row], h[col] into sEin (float4 coalesced) ---
        for (int idx = tid; idx < TILE * 32; idx += TPB) {
            int e2 = idx >> 5;
            int part = idx & 31;
            int r = sRow[e2];
            if (r >= 0) {
                if (part < 16) {
                    float4 v = *(const float4*)(h + (long)r * 64 + part * 4);
                    *(float4*)(sEin + e2 * 132 + part * 4) = v;
                } else {
                    int c = sCol[e2];
                    float4 v = *(const float4*)(h + (long)c * 64 + (part - 16) * 4);
                    *(float4*)(sEin + e2 * 132 + 64 + (part - 16) * 4) = v;
                }
            }
        }
        __syncthreads();

        // --- layer 1: e_in[129] @ We1 -> relu ---
        const float* ein = sEin + el * 132;
        float4 a0 = *(float4*)(sB + j0);
        float4 a1 = *(float4*)(sB + j0 + 4);
        #pragma unroll 4
        for (int k = 0; k < KE; k++) {
            float a = ein[k];
            float4 w0 = *(float4*)(sWe1 + k * 64 + j0);
            float4 w1 = *(float4*)(sWe1 + k * 64 + j0 + 4);
            a0.x += a * w0.x; a0.y += a * w0.y; a0.z += a * w0.z; a0.w += a * w0.w;
            a1.x += a * w1.x; a1.y += a * w1.y; a1.z += a * w1.z; a1.w += a * w1.w;
        }
        a0.x = fmaxf(a0.x, 0.f); a0.y = fmaxf(a0.y, 0.f); a0.z = fmaxf(a0.z, 0.f); a0.w = fmaxf(a0.w, 0.f);
        a1.x = fmaxf(a1.x, 0.f); a1.y = fmaxf(a1.y, 0.f); a1.z = fmaxf(a1.z, 0.f); a1.w = fmaxf(a1.w, 0.f);
        *(float4*)(sHid + el * 68 + j0)     = a0;
        *(float4*)(sHid + el * 68 + j0 + 4) = a1;
        __syncthreads();

        // --- layer 2: hid1 @ We2 -> relu = edge_feat ---
        float4 f0 = *(float4*)(sB + 64 + j0);
        float4 f1 = *(float4*)(sB + 64 + j0 + 4);
        const float* hid = sHid + el * 68;
        #pragma unroll 4
        for (int k = 0; k < 64; k++) {
            float a = hid[k];
            float4 w0 = *(float4*)(sWe2 + k * 64 + j0);
            float4 w1 = *(float4*)(sWe2 + k * 64 + j0 + 4);
            f0.x += a * w0.x; f0.y += a * w0.y; f0.z += a * w0.z; f0.w += a * w0.w;
            f1.x += a * w1.x; f1.y += a * w1.y; f1.z += a * w1.z; f1.w += a * w1.w;
        }
        f0.x = fmaxf(f0.x, 0.f); f0.y = fmaxf(f0.y, 0.f); f0.z = fmaxf(f0.z, 0.f); f0.w = fmaxf(f0.w, 0.f);
        f1.x = fmaxf(f1.x, 0.f); f1.y = fmaxf(f1.y, 0.f); f1.z = fmaxf(f1.z, 0.f); f1.w = fmaxf(f1.w, 0.f);
        *(float4*)(sEin + el * 132 + j0)     = f0;   // reuse sEin as edge_feat store
        *(float4*)(sEin + el * 132 + j0 + 4) = f1;
        __syncthreads();

        // --- layer 3 (gate head): relu(feat @ Wc1 + bc1) @ Wc2 + bc2 ---
        float4 c0 = *(float4*)(sB + 128 + j0);
        float4 c1 = *(float4*)(sB + 128 + j0 + 4);
        const float* feat = sEin + el * 132;
        #pragma unroll 4
        for (int k = 0; k < 64; k++) {
            float a = feat[k];
            float4 w0 = *(float4*)(sWc1 + k * 64 + j0);
            float4 w1 = *(float4*)(sWc1 + k * 64 + j0 + 4);
            c0.x += a * w0.x; c0.y += a * w0.y; c0.z += a * w0.z; c0.w += a * w0.w;
            c1.x += a * w1.x; c1.y += a * w1.y; c1.z += a * w1.z; c1.w += a * w1.w;
        }
        float4 v2 = *(float4*)(sWc2 + j0);
        float4 v3 = *(float4*)(sWc2 + j0 + 4);
        float partial =
            fmaxf(c0.x, 0.f) * v2.x + fmaxf(c0.y, 0.f) * v2.y +
            fmaxf(c0.z, 0.f) * v2.z + fmaxf(c0.w, 0.f) * v2.w +
            fmaxf(c1.x, 0.f) * v3.x + fmaxf(c1.y, 0.f) * v3.y +
            fmaxf(c1.z, 0.f) * v3.z + fmaxf(c1.w, 0.f) * v3.w;
        partial += __shfl_down_sync(0xffffffffu, partial, 4, 8);
        partial += __shfl_down_sync(0xffffffffu, partial, 2, 8);
        partial += __shfl_down_sync(0xffffffffu, partial, 1, 8);

        // --- scatter ---
        int e = ebase + el;
        if (e < E) {
            int r = sRow[el];
            float* dst = g_agg_h + (long)r * 64 + j0;
            atomicAdd(dst + 0, f0.x); atomicAdd(dst + 1, f0.y);
            atomicAdd(dst + 2, f0.z); atomicAdd(dst + 3, f0.w);
            atomicAdd(dst + 4, f1.x); atomicAdd(dst + 5, f1.y);
            atomicAdd(dst + 6, f1.z); atomicAdd(dst + 7, f1.w);
            if (jg == 0) {
                float gate = partial + bc2v;
                #pragma unroll
                for (int d = 0; d < 3; d++) {
                    float tr = sDiff[el * 3 + d] * gate;
                    tr = fminf(fmaxf(tr, -100.f), 100.f);
                    atomicAdd(&g_sum_t[r * 3 + d], tr);
                }
                atomicAdd(&g_cnt[r], 1.0f);
            }
        }
    }
}

// ---------------------------------------------------------------------------
// Node kernel: h_out = h + MLP([h, agg_h])
// smem floats: Wn1 8192 | Wn2 4096 | biases 128 | In 32*132 | Hid 32*68
// = 18816 floats = 75264 bytes
// ---------------------------------------------------------------------------
__global__ __launch_bounds__(TPB, 3) void node_kernel(
    const float* __restrict__ h,
    const float* __restrict__ Wn1, const float* __restrict__ bn1,
    const float* __restrict__ Wn2, const float* __restrict__ bn2,
    float* __restrict__ out_h, int N)
{
    extern __shared__ float sm[];
    float* sWn1 = sm;                       // 128*64
    float* sWn2 = sWn1 + 128 * 64;          // 64*64
    float* sB   = sWn2 + 64 * 64;           // bn1(64) bn2(64)
    float* sIn  = sB + 128;                 // 32*132
    float* sHid = sIn + TILE * 132;         // 32*68

    const int tid = threadIdx.x;
    for (int i = tid; i < 128 * 64; i += TPB) sWn1[i] = Wn1[i];
    for (int i = tid; i < 64 * 64; i += TPB)  sWn2[i] = Wn2[i];
    if (tid < 64)        sB[tid] = bn1[tid];
    else if (tid < 128)  sB[tid] = bn2[tid - 64];

    const int nl = tid >> 3;
    const int jg = tid & 7;
    const int j0 = jg * 8;

    const int ntiles = (N + TILE - 1) / TILE;
    for (int t = blockIdx.x; t < ntiles; t += gridDim.x) {
        const int nbase = t * TILE;
        __syncthreads();

        for (int idx = tid; idx < TILE * 32; idx += TPB) {
            int n2 = idx >> 5;
            int part = idx & 31;
            int node = nbase + n2;
            if (node < N) {
                if (part < 16) {
                    float4 v = *(const float4*)(h + (long)node * 64 + part * 4);
                    *(float4*)(sIn + n2 * 132 + part * 4) = v;
                } else {
                    float4 v = *(const float4*)(g_agg_h + (long)node * 64 + (part - 16) * 4);
                    *(float4*)(sIn + n2 * 132 + 64 + (part - 16) * 4) = v;
                }
            }
        }
        __syncthreads();

        const float* nin = sIn + nl * 132;
        float4 a0 = *(float4*)(sB + j0);
        float4 a1 = *(float4*)(sB + j0 + 4);
        #pragma unroll 4
        for (int k = 0; k < 128; k++) {
            float a = nin[k];
            float4 w0 = *(float4*)(sWn1 + k * 64 + j0);
            float4 w1 = *(float4*)(sWn1 + k * 64 + j0 + 4);
            a0.x += a * w0.x; a0.y += a * w0.y; a0.z += a * w0.z; a0.w += a * w0.w;
            a1.x += a * w1.x; a1.y += a * w1.y; a1.z += a * w1.z; a1.w += a * w1.w;
        }
        a0.x = fmaxf(a0.x, 0.f); a0.y = fmaxf(a0.y, 0.f); a0.z = fmaxf(a0.z, 0.f); a0.w = fmaxf(a0.w, 0.f);
        a1.x = fmaxf(a1.x, 0.f); a1.y = fmaxf(a1.y, 0.f); a1.z = fmaxf(a1.z, 0.f); a1.w = fmaxf(a1.w, 0.f);
        *(float4*)(sHid + nl * 68 + j0)     = a0;
        *(float4*)(sHid + nl * 68 + j0 + 4) = a1;
        __syncthreads();

        float4 o0 = *(float4*)(sB + 64 + j0);
        float4 o1 = *(float4*)(sB + 64 + j0 + 4);
        const float* hid = sHid + nl * 68;
        #pragma unroll 4
        for (int k = 0; k < 64; k++) {
            float a = hid[k];
            float4 w0 = *(float4*)(sWn2 + k * 64 + j0);
            float4 w1 = *(float4*)(sWn2 + k * 64 + j0 + 4);
            o0.x += a * w0.x; o0.y += a * w0.y; o0.z += a * w0.z; o0.w += a * w0.w;
            o1.x += a * w1.x; o1.y += a * w1.y; o1.z += a * w1.z; o1.w += a * w1.w;
        }
        int node = nbase + nl;
        if (node < N) {
            // residual: + h (first 64 of sIn row)
            o0.x += nin[j0 + 0]; o0.y += nin[j0 + 1]; o0.z += nin[j0 + 2]; o0.w += nin[j0 + 3];
            o1.x += nin[j0 + 4]; o1.y += nin[j0 + 5]; o1.z += nin[j0 + 6]; o1.w += nin[j0 + 7];
            *(float4*)(out_h + (long)node * 64 + j0)     = o0;
            *(float4*)(out_h + (long)node * 64 + j0 + 4) = o1;
        }
    }
}

// ---------------------------------------------------------------------------
// Coord/velocity kernel
// ---------------------------------------------------------------------------
__global__ void coord_kernel(const float* __restrict__ coord,
                             const float* __restrict__ vel,
                             float* __restrict__ out_coord,
                             float* __restrict__ out_v, int N)
{
    int i = blockIdx.x * blockDim.x + threadIdx.x;
    if (i < N) {
        float c = g_cnt[i];
        float invc = (c > 0.f) ? (1.f / fmaxf(c, 1.f)) : 0.f;
        #pragma unroll
        for (int d = 0; d < 3; d++) {
            float agg = g_sum_t[i * 3 + d] * invc;  // COORDS_WEIGHT = 1
            float v = vel[i * 3 + d] + agg * 0.125f;   // * 1/N_LAYERS
            out_v[i * 3 + d] = v;
            out_coord[i * 3 + d] = coord[i * 3 + d] + v * 0.125f;
        }
    }
}

// ---------------------------------------------------------------------------
extern "C" void kernel_launch(void* const* d_in, const int* in_sizes, int n_in,
                              void* d_out, int out_size)
{
    const float* h     = (const float*)d_in[0];
    const float* coord = (const float*)d_in[1];
    const float* vel   = (const float*)d_in[2];
    // d_in[3] = vel_init (unused by reference)
    const int*   eidx  = (const int*)d_in[4];
    const float* We1 = (const float*)d_in[5];
    const float* be1 = (const float*)d_in[6];
    const float* We2 = (const float*)d_in[7];
    const float* be2 = (const float*)d_in[8];
    const float* Wn1 = (const float*)d_in[9];
    const float* bn1 = (const float*)d_in[10];
    const float* Wn2 = (const float*)d_in[11];
    const float* bn2 = (const float*)d_in[12];
    const float* Wc1 = (const float*)d_in[13];
    const float* bc1 = (const float*)d_in[14];
    const float* Wc2 = (const float*)d_in[15];
    const float* bc2 = (const float*)d_in[16];

    const int N = in_sizes[0] / 64;
    const int E = in_sizes[4] / 2;

    float* out      = (float*)d_out;
    float* out_h    = out;
    float* out_coord = out + (long)N * 64;
    float* out_v    = out_coord + (long)N * 3;

    const size_t smE = (size_t)(129*64 + 64*64 + 64*64 + 64 + 192
                                + TILE*132 + TILE*68 + 96 + 64) * sizeof(float); // 93056
    const size_t smN = (size_t)(128*64 + 64*64 + 128
                                + TILE*132 + TILE*68) * sizeof(float);           // 75264

    cudaFuncSetAttribute(edge_kernel, cudaFuncAttributeMaxDynamicSharedMemorySize, (int)smE);
    cudaFuncSetAttribute(node_kernel, cudaFuncAttributeMaxDynamicSharedMemorySize, (int)smN);

    zero_kernel<<<512, 256>>>(N);
    edge_kernel<<<304, TPB, smE>>>(h, coord, eidx, E,
                                   We1, be1, We2, be2, Wc1, bc1, Wc2, bc2);
    node_kernel<<<456, TPB, smN>>>(h, Wn1, bn1, Wn2, bn2, out_h, N);
    coord_kernel<<<(N + 255) / 256, 256>>>(coord, vel, out_coord, out_v, N);
}

// round 2
// speedup vs baseline: 1.9265x; 1.9265x over previous
#include <cuda_runtime.h>

#define TPB 256
#define NMAX 50048

typedef unsigned long long u64;

__device__ float  g_agg_h[(size_t)NMAX * 64];
__device__ float4 g_sum4[NMAX];

// ---------------------------------------------------------------------------
// f32x2 packed-FMA helpers (sm_103a; ptxas never emits FFMA2 from C++)
// ---------------------------------------------------------------------------
__device__ __forceinline__ u64 pk2(float x) {
    u64 r; asm("mov.b64 %0,{%1,%1};" : "=l"(r) : "f"(x)); return r;
}
__device__ __forceinline__ void fma2(u64 &d, u64 a, u64 b) {
    asm("fma.rn.f32x2 %0,%1,%2,%0;" : "+l"(d) : "l"(a), "l"(b));
}
__device__ __forceinline__ float2 up2(u64 v) {
    float2 f; asm("mov.b64 {%0,%1},%2;" : "=f"(f.x), "=f"(f.y) : "l"(v)); return f;
}

// one K-step: 2 edges/nodes share weights; 8 outputs each (4 f32x2 pairs)
__device__ __forceinline__ void step2(u64 A[2][4], float x0, float x1, const float* w) {
    ulonglong2 w01 = *(const ulonglong2*)(w);
    ulonglong2 w23 = *(const ulonglong2*)(w + 4);
    u64 p0 = pk2(x0), p1 = pk2(x1);
    fma2(A[0][0], p0, w01.x); fma2(A[0][1], p0, w01.y);
    fma2(A[0][2], p0, w23.x); fma2(A[0][3], p0, w23.y);
    fma2(A[1][0], p1, w01.x); fma2(A[1][1], p1, w01.y);
    fma2(A[1][2], p1, w23.x); fma2(A[1][3], p1, w23.y);
}

__device__ __forceinline__ void initA(u64 A[2][4], const float* b) {
    ulonglong2 b01 = *(const ulonglong2*)b;
    ulonglong2 b23 = *(const ulonglong2*)(b + 4);
    A[0][0] = A[1][0] = b01.x; A[0][1] = A[1][1] = b01.y;
    A[0][2] = A[1][2] = b23.x; A[0][3] = A[1][3] = b23.y;
}

template<int K>
__device__ __forceinline__ void gemm_rows(u64 A[2][4], const float* r0, const float* r1,
                                          const float* Wb, int j0) {
    #pragma unroll 2
    for (int k0 = 0; k0 < K; k0 += 4) {
        float4 a0 = *(const float4*)(r0 + k0);
        float4 a1 = *(const float4*)(r1 + k0);
        step2(A, a0.x, a1.x, Wb + (k0 + 0) * 64 + j0);
        step2(A, a0.y, a1.y, Wb + (k0 + 1) * 64 + j0);
        step2(A, a0.z, a1.z, Wb + (k0 + 2) * 64 + j0);
        step2(A, a0.w, a1.w, Wb + (k0 + 3) * 64 + j0);
    }
}

__device__ __forceinline__ void relu_store2(u64 A[2][4], float* d0, float* d1, int j0) {
    #pragma unroll
    for (int p = 0; p < 4; p++) {
        float2 v0 = up2(A[0][p]);
        v0.x = fmaxf(v0.x, 0.f); v0.y = fmaxf(v0.y, 0.f);
        *(float2*)(d0 + j0 + 2 * p) = v0;
        float2 v1 = up2(A[1][p]);
        v1.x = fmaxf(v1.x, 0.f); v1.y = fmaxf(v1.y, 0.f);
        *(float2*)(d1 + j0 + 2 * p) = v1;
    }
}

// ---------------------------------------------------------------------------
// Zero the scatter accumulators (float4-vectorized)
// ---------------------------------------------------------------------------
__global__ void zero_kernel(int n) {
    int total = n * 17;   // n*16 float4 for agg_h + n float4 for sum4
    int stride = gridDim.x * blockDim.x;
    float4 z = make_float4(0.f, 0.f, 0.f, 0.f);
    for (int i = blockIdx.x * blockDim.x + threadIdx.x; i < total; i += stride) {
        if (i < n * 16) ((float4*)g_agg_h)[i] = z;
        else            g_sum4[i - n * 16] = z;
    }
}

// ---------------------------------------------------------------------------
// Edge kernel: warp-private 8-edge tiles; thread = (2 edges) x (8 outputs)
// smem floats: We1 8256 | We2 4096 | Wc1 4096 | Wc2 64 | biases 192
//              | act 8 warps * 8 edges * 132  = 25152 floats = 100608 B
// ---------------------------------------------------------------------------
__global__ __launch_bounds__(TPB, 2) void edge_kernel(
    const float* __restrict__ h, const float* __restrict__ coord,
    const int* __restrict__ eidx, int E,
    const float* __restrict__ We1, const float* __restrict__ be1,
    const float* __restrict__ We2, const float* __restrict__ be2,
    const float* __restrict__ Wc1, const float* __restrict__ bc1,
    const float* __restrict__ Wc2, const float* __restrict__ bc2)
{
    extern __shared__ float sm[];
    float* sWe1 = sm;                  // 129*64
    float* sWe2 = sWe1 + 129 * 64;     // 64*64
    float* sWc1 = sWe2 + 64 * 64;      // 64*64
    float* sWc2 = sWc1 + 64 * 64;      // 64
    float* sB   = sWc2 + 64;           // be1 | be2 | bc1
    float* sAct = sB + 192;            // 8 * 8 * 132

    const int tid = threadIdx.x;
    for (int i = tid; i < 129 * 64; i += TPB) sWe1[i] = We1[i];
    for (int i = tid; i < 64 * 64; i += TPB)  sWe2[i] = We2[i];
    for (int i = tid; i < 64 * 64; i += TPB)  sWc1[i] = Wc1[i];
    if (tid < 64)        sWc2[tid] = Wc2[tid];
    if (tid < 64)        sB[tid] = be1[tid];
    else if (tid < 128)  sB[tid] = be2[tid - 64];
    else if (tid < 192)  sB[tid] = bc1[tid - 128];
    const float bc2v = bc2[0];
    __syncthreads();

    const int warp = tid >> 5, lane = tid & 31;
    const int eq = lane >> 3, jg = lane & 7, j0 = jg * 8;
    float* W = sAct + warp * (8 * 132);
    const unsigned FULL = 0xffffffffu;

    const int ngroups = (E + 7) >> 3;
    const int nwarps = gridDim.x * (TPB / 32);

    for (int g = blockIdx.x * (TPB / 32) + warp; g < ngroups; g += nwarps) {
        const int ebase = g * 8;

        // --- lanes 0..7: indices, coord diff, radial ---
        int rreg = -1, creg = 0;
        float dxr = 0.f, dyr = 0.f, dzr = 0.f;
        if (lane < 8) {
            int e = ebase + lane;
            float rad = 0.f;
            if (e < E) {
                rreg = eidx[e]; creg = eidx[E + e];
                dxr = coord[rreg * 3 + 0] - coord[creg * 3 + 0];
                dyr = coord[rreg * 3 + 1] - coord[creg * 3 + 1];
                dzr = coord[rreg * 3 + 2] - coord[creg * 3 + 2];
                rad = dxr * dxr + dyr * dyr + dzr * dzr;
            }
            W[lane * 132 + 128] = rad;
        }
        __syncwarp();

        // --- gather h[row]||h[col] into warp-private rows ---
        #pragma unroll
        for (int i = 0; i < 8; i++) {
            int r = __shfl_sync(FULL, rreg, i);
            int c = __shfl_sync(FULL, creg, i);
            if (r < 0) continue;   // uniform
            const float* src = (lane < 16) ? (h + (size_t)r * 64 + lane * 4)
                                           : (h + (size_t)c * 64 + (lane - 16) * 4);
            float4 v = *(const float4*)src;
            float* dst = (lane < 16) ? (W + i * 132 + lane * 4)
                                     : (W + i * 132 + 64 + (lane - 16) * 4);
            *(float4*)dst = v;
        }
        __syncwarp();

        float* r0 = W + (2 * eq) * 132;
        float* r1 = r0 + 132;
        const bool v0ok = (ebase + 2 * eq) < E;
        const bool v1ok = (ebase + 2 * eq + 1) < E;

        // --- layer 1: [129] -> 64, relu ---
        u64 A[2][4];
        initA(A, sB + j0);
        gemm_rows<128>(A, r0, r1, sWe1, j0);
        step2(A, r0[128], r1[128], sWe1 + 128 * 64 + j0);   // radial term
        __syncwarp();
        relu_store2(A, r0, r1, j0);    // hid overwrites ein[0..63]
        __syncwarp();

        // --- layer 2: 64 -> 64, relu = edge_feat ---
        u64 F[2][4];
        initA(F, sB + 64 + j0);
        gemm_rows<64>(F, r0, r1, sWe2, j0);

        float2 f00 = up2(F[0][0]), f01 = up2(F[0][1]), f02 = up2(F[0][2]), f03 = up2(F[0][3]);
        float2 f10 = up2(F[1][0]), f11 = up2(F[1][1]), f12 = up2(F[1][2]), f13 = up2(F[1][3]);
        float4 q0l = make_float4(fmaxf(f00.x,0.f), fmaxf(f00.y,0.f), fmaxf(f01.x,0.f), fmaxf(f01.y,0.f));
        float4 q0h = make_float4(fmaxf(f02.x,0.f), fmaxf(f02.y,0.f), fmaxf(f03.x,0.f), fmaxf(f03.y,0.f));
        float4 q1l = make_float4(fmaxf(f10.x,0.f), fmaxf(f10.y,0.f), fmaxf(f11.x,0.f), fmaxf(f11.y,0.f));
        float4 q1h = make_float4(fmaxf(f12.x,0.f), fmaxf(f12.y,0.f), fmaxf(f13.x,0.f), fmaxf(f13.y,0.f));

        // store feat into rows at [64..127] (ein dead, hid still live at [0..63])
        *(float4*)(r0 + 64 + j0)     = q0l;
        *(float4*)(r0 + 64 + j0 + 4) = q0h;
        *(float4*)(r1 + 64 + j0)     = q1l;
        *(float4*)(r1 + 64 + j0 + 4) = q1h;

        // scatter agg_h with vector atomics
        int rr0 = __shfl_sync(FULL, rreg, 2 * eq);
        int rr1 = __shfl_sync(FULL, rreg, 2 * eq + 1);
        if (v0ok) {
            atomicAdd((float4*)(g_agg_h + (size_t)rr0 * 64 + j0),     q0l);
            atomicAdd((float4*)(g_agg_h + (size_t)rr0 * 64 + j0 + 4), q0h);
        }
        if (v1ok) {
            atomicAdd((float4*)(g_agg_h + (size_t)rr1 * 64 + j0),     q1l);
            atomicAdd((float4*)(g_agg_h + (size_t)rr1 * 64 + j0 + 4), q1h);
        }
        __syncwarp();

        // --- layer 3 (gate): relu(feat @ Wc1 + bc1) . Wc2 + bc2 ---
        u64 C[2][4];
        initA(C, sB + 128 + j0);
        gemm_rows<64>(C, r0 + 64, r1 + 64, sWc1, j0);

        float pg0 = 0.f, pg1 = 0.f;
        #pragma unroll
        for (int p = 0; p < 4; p++) {
            float2 c0 = up2(C[0][p]);
            float2 c1 = up2(C[1][p]);
            float2 w2 = *(const float2*)(sWc2 + j0 + 2 * p);
            pg0 += fmaxf(c0.x, 0.f) * w2.x + fmaxf(c0.y, 0.f) * w2.y;
            pg1 += fmaxf(c1.x, 0.f) * w2.x + fmaxf(c1.y, 0.f) * w2.y;
        }
        pg0 += __shfl_down_sync(FULL, pg0, 4, 8);
        pg0 += __shfl_down_sync(FULL, pg0, 2, 8);
        pg0 += __shfl_down_sync(FULL, pg0, 1, 8);
        pg1 += __shfl_down_sync(FULL, pg1, 4, 8);
        pg1 += __shfl_down_sync(FULL, pg1, 2, 8);
        pg1 += __shfl_down_sync(FULL, pg1, 1, 8);

        float dX0 = __shfl_sync(FULL, dxr, 2 * eq), dY0 = __shfl_sync(FULL, dyr, 2 * eq), dZ0 = __shfl_sync(FULL, dzr, 2 * eq);
        float dX1 = __shfl_sync(FULL, dxr, 2 * eq + 1), dY1 = __shfl_sync(FULL, dyr, 2 * eq + 1), dZ1 = __shfl_sync(FULL, dzr, 2 * eq + 1);

        if (jg == 0) {
            if (v0ok) {
                float gt = pg0 + bc2v;
                float4 t = make_float4(
                    fminf(fmaxf(dX0 * gt, -100.f), 100.f),
                    fminf(fmaxf(dY0 * gt, -100.f), 100.f),
                    fminf(fmaxf(dZ0 * gt, -100.f), 100.f), 1.f);
                atomicAdd(&g_sum4[rr0], t);
            }
            if (v1ok) {
                float gt = pg1 + bc2v;
                float4 t = make_float4(
                    fminf(fmaxf(dX1 * gt, -100.f), 100.f),
                    fminf(fmaxf(dY1 * gt, -100.f), 100.f),
                    fminf(fmaxf(dZ1 * gt, -100.f), 100.f), 1.f);
                atomicAdd(&g_sum4[rr1], t);
            }
        }
    }
}

// ---------------------------------------------------------------------------
// Node kernel: h_out = h + MLP([h, agg_h]); warp-private 8-node tiles
// smem floats: Wn1 8192 | Wn2 4096 | biases 128 | act 8*8*200 = 25216 = 100864 B
// ---------------------------------------------------------------------------
#define NLD 200
__global__ __launch_bounds__(TPB, 2) void node_kernel(
    const float* __restrict__ h,
    const float* __restrict__ Wn1, const float* __restrict__ bn1,
    const float* __restrict__ Wn2, const float* __restrict__ bn2,
    float* __restrict__ out_h, int N)
{
    extern __shared__ float sm[];
    float* sWn1 = sm;                  // 128*64
    float* sWn2 = sWn1 + 128 * 64;     // 64*64
    float* sB   = sWn2 + 64 * 64;      // bn1 | bn2
    float* sAct = sB + 128;            // 8 * 8 * 200

    const int tid = threadIdx.x;
    for (int i = tid; i < 128 * 64; i += TPB) sWn1[i] = Wn1[i];
    for (int i = tid; i < 64 * 64; i += TPB)  sWn2[i] = Wn2[i];
    if (tid < 64)        sB[tid] = bn1[tid];
    else if (tid < 128)  sB[tid] = bn2[tid - 64];
    __syncthreads();

    const int warp = tid >> 5, lane = tid & 31;
    const int eq = lane >> 3, jg = lane & 7, j0 = jg * 8;
    float* W = sAct + warp * (8 * NLD);

    const int ngroups = (N + 7) >> 3;
    const int nwarps = gridDim.x * (TPB / 32);

    for (int g = blockIdx.x * (TPB / 32) + warp; g < ngroups; g += nwarps) {
        const int nbase = g * 8;

        #pragma unroll
        for (int i = 0; i < 8; i++) {
            int node = nbase + i;
            if (node >= N) continue;   // uniform
            const float* src = (lane < 16) ? (h + (size_t)node * 64 + lane * 4)
                                           : (g_agg_h + (size_t)node * 64 + (lane - 16) * 4);
            float4 v = *(const float4*)src;
            float* dst = (lane < 16) ? (W + i * NLD + lane * 4)
                                     : (W + i * NLD + 64 + (lane - 16) * 4);
            *(float4*)dst = v;
        }
        __syncwarp();

        float* r0 = W + (2 * eq) * NLD;
        float* r1 = r0 + NLD;
        const int n0 = nbase + 2 * eq, n1 = n0 + 1;

        // layer 1: [128] -> 64, relu -> rows [128..191]
        u64 A[2][4];
        initA(A, sB + j0);
        gemm_rows<128>(A, r0, r1, sWn1, j0);
        relu_store2(A, r0 + 128, r1 + 128, j0);
        __syncwarp();

        // layer 2: 64 -> 64, + residual h
        u64 O[2][4];
        initA(O, sB + 64 + j0);
        gemm_rows<64>(O, r0 + 128, r1 + 128, sWn2, j0);

        if (n0 < N) {
            float2 o0 = up2(O[0][0]), o1 = up2(O[0][1]), o2 = up2(O[0][2]), o3 = up2(O[0][3]);
            float4 lo = make_float4(o0.x + r0[j0+0], o0.y + r0[j0+1], o1.x + r0[j0+2], o1.y + r0[j0+3]);
            float4 hi = make_float4(o2.x + r0[j0+4], o2.y + r0[j0+5], o3.x + r0[j0+6], o3.y + r0[j0+7]);
            *(float4*)(out_h + (size_t)n0 * 64 + j0)     = lo;
            *(float4*)(out_h + (size_t)n0 * 64 + j0 + 4) = hi;
        }
        if (n1 < N) {
            float2 o0 = up2(O[1][0]), o1 = up2(O[1][1]), o2 = up2(O[1][2]), o3 = up2(O[1][3]);
            float4 lo = make_float4(o0.x + r1[j0+0], o0.y + r1[j0+1], o1.x + r1[j0+2], o1.y + r1[j0+3]);
            float4 hi = make_float4(o2.x + r1[j0+4], o2.y + r1[j0+5], o3.x + r1[j0+6], o3.y + r1[j0+7]);
            *(float4*)(out_h + (size_t)n1 * 64 + j0)     = lo;
            *(float4*)(out_h + (size_t)n1 * 64 + j0 + 4) = hi;
        }
    }
}

// ---------------------------------------------------------------------------
// Coord/velocity kernel
// ---------------------------------------------------------------------------
__global__ void coord_kernel(const float* __restrict__ coord,
                             const float* __restrict__ vel,
                             float* __restrict__ out_coord,
                             float* __restrict__ out_v, int N)
{
    int i = blockIdx.x * blockDim.x + threadIdx.x;
    if (i < N) {
        float4 s = g_sum4[i];
        float c = s.w;
        float invc = (c > 0.f) ? (1.f / fmaxf(c, 1.f)) : 0.f;
        float ax = s.x * invc, ay = s.y * invc, az = s.z * invc;
        float vx = vel[i * 3 + 0] + ax * 0.125f;
        float vy = vel[i * 3 + 1] + ay * 0.125f;
        float vz = vel[i * 3 + 2] + az * 0.125f;
        out_v[i * 3 + 0] = vx;
        out_v[i * 3 + 1] = vy;
        out_v[i * 3 + 2] = vz;
        out_coord[i * 3 + 0] = coord[i * 3 + 0] + vx * 0.125f;
        out_coord[i * 3 + 1] = coord[i * 3 + 1] + vy * 0.125f;
        out_coord[i * 3 + 2] = coord[i * 3 + 2] + vz * 0.125f;
    }
}

// ---------------------------------------------------------------------------
extern "C" void kernel_launch(void* const* d_in, const int* in_sizes, int n_in,
                              void* d_out, int out_size)
{
    const float* h     = (const float*)d_in[0];
    const float* coord = (const float*)d_in[1];
    const float* vel   = (const float*)d_in[2];
    const int*   eidx  = (const int*)d_in[4];
    const float* We1 = (const float*)d_in[5];
    const float* be1 = (const float*)d_in[6];
    const float* We2 = (const float*)d_in[7];
    const float* be2 = (const float*)d_in[8];
    const float* Wn1 = (const float*)d_in[9];
    const float* bn1 = (const float*)d_in[10];
    const float* Wn2 = (const float*)d_in[11];
    const float* bn2 = (const float*)d_in[12];
    const float* Wc1 = (const float*)d_in[13];
    const float* bc1 = (const float*)d_in[14];
    const float* Wc2 = (const float*)d_in[15];
    const float* bc2 = (const float*)d_in[16];

    const int N = in_sizes[0] / 64;
    const int E = in_sizes[4] / 2;

    float* out       = (float*)d_out;
    float* out_h     = out;
    float* out_coord = out + (size_t)N * 64;
    float* out_v     = out_coord + (size_t)N * 3;

    const size_t smE = (size_t)(129*64 + 64*64 + 64*64 + 64 + 192 + 8*8*132) * sizeof(float);  // 100608
    const size_t smN = (size_t)(128*64 + 64*64 + 128 + 8*8*NLD) * sizeof(float);               // 100864

    cudaFuncSetAttribute(edge_kernel, cudaFuncAttributeMaxDynamicSharedMemorySize, (int)smE);
    cudaFuncSetAttribute(node_kernel, cudaFuncAttributeMaxDynamicSharedMemorySize, (int)smN);

    zero_kernel<<<512, 256>>>(N);
    edge_kernel<<<296, TPB, smE>>>(h, coord, eidx, E,
                                   We1, be1, We2, be2, Wc1, bc1, Wc2, bc2);
    node_kernel<<<296, TPB, smN>>>(h, Wn1, bn1, Wn2, bn2, out_h, N);
    coord_kernel<<<(N + 255) / 256, 256>>>(coord, vel, out_coord, out_v, N);
}

// round 4
// speedup vs baseline: 9.3817x; 4.8699x over previous
#include <cuda_runtime.h>
#include <cuda_bf16.h>
#include <cstdint>

typedef unsigned long long u64;
#define FULLM 0xffffffffu

#define NMAX 50048
__device__ float  g_agg_h[(size_t)NMAX * 64];
__device__ float4 g_sum4[NMAX];

// ===========================================================================
// smem layout for edge kernel (byte offsets)
// weight planes: 64 rows x 128B (64 bf16 k), SW-swizzled; hi plane, lo = +8192
// ===========================================================================
#define W1A_HI   0
#define W1B_HI   16384
#define W2_HI    32768
#define WC_HI    49152
#define A_OFF    65536        // per warp: 8192 (hi 4096 | lo 4096)
#define MISC_OFF 131072       // fp32: be1[64] be2[64] bc1[64] wc2[64] w1rad[64]
#define SMEM_E   (131072 + 1280)

__device__ __forceinline__ uint32_t smem_to_u32(const void* p) {
    uint32_t a;
    asm("{ .reg .u64 t; cvta.to.shared.u64 t, %1; cvt.u32.u64 %0, t; }" : "=r"(a) : "l"(p));
    return a;
}
__device__ __forceinline__ void ldsm4(uint32_t r[4], uint32_t addr) {
    asm volatile("ldmatrix.sync.aligned.m8n8.x4.shared.b16 {%0,%1,%2,%3}, [%4];"
        : "=r"(r[0]), "=r"(r[1]), "=r"(r[2]), "=r"(r[3]) : "r"(addr));
}
__device__ __forceinline__ void mma_bf16(float c[4], const uint32_t a[4],
                                         uint32_t b0, uint32_t b1) {
    asm volatile("mma.sync.aligned.m16n8k16.row.col.f32.bf16.bf16.f32 "
        "{%0,%1,%2,%3},{%4,%5,%6,%7},{%8,%9},{%0,%1,%2,%3};"
        : "+f"(c[0]), "+f"(c[1]), "+f"(c[2]), "+f"(c[3])
        : "r"(a[0]), "r"(a[1]), "r"(a[2]), "r"(a[3]), "r"(b0), "r"(b1));
}
// pack 2 floats -> bf16x2 hi + bf16x2 lo (residual)
__device__ __forceinline__ void packhl(float a, float b, uint32_t &hi, uint32_t &lo) {
    __nv_bfloat162 hh = __floats2bfloat162_rn(a, b);
    float ra = a - __bfloat162float(hh.x);
    float rb = b - __bfloat162float(hh.y);
    __nv_bfloat162 ll = __floats2bfloat162_rn(ra, rb);
    hi = *(uint32_t*)&hh;
    lo = *(uint32_t*)&ll;
}
// weight element (output j as row, k as col) -> hi/lo planes, swizzled
__device__ __forceinline__ void putw(char* sm, int plane, int j, int k, float x) {
    __nv_bfloat16 hb = __float2bfloat16(x);
    __nv_bfloat16 lb = __float2bfloat16(x - __bfloat162float(hb));
    uint32_t off = (uint32_t)(j * 128 + ((k * 2) ^ ((j & 7) << 4)));
    *(__nv_bfloat16*)(sm + plane + off) = hb;
    *(__nv_bfloat16*)(sm + plane + 8192 + off) = lb;
}

// ===========================================================================
// Edge kernel: mma.sync bf16x3; warp = 32 edges x 64 outs; persistent
// ===========================================================================
__global__ __launch_bounds__(256, 1) void edge_mma_kernel(
    const float* __restrict__ h, const float* __restrict__ coord,
    const int* __restrict__ eidx, int E,
    const float* __restrict__ We1, const float* __restrict__ be1,
    const float* __restrict__ We2, const float* __restrict__ be2,
    const float* __restrict__ Wc1, const float* __restrict__ bc1,
    const float* __restrict__ Wc2, const float* __restrict__ bc2)
{
    extern __shared__ char sm[];
    const uint32_t smb = smem_to_u32(sm);
    const int tid = threadIdx.x;
    float* sMisc = (float*)(sm + MISC_OFF);

    // ---- stage weights (transpose to [j][k], bf16 split) ----
    for (int i = tid; i < 129 * 64; i += 256) {
        int k = i >> 6, j = i & 63;
        float x = We1[i];
        if (k < 128) putw(sm, (k < 64) ? W1A_HI : W1B_HI, j, k & 63, x);
        else         sMisc[256 + j] = x;           // radial row, fp32
    }
    for (int i = tid; i < 64 * 64; i += 256) {
        int k = i >> 6, j = i & 63;
        putw(sm, W2_HI, j, k, We2[i]);
        putw(sm, WC_HI, j, k, Wc1[i]);
    }
    if (tid < 64)        sMisc[tid] = be1[tid];
    else if (tid < 128)  sMisc[tid] = be2[tid - 64];
    else if (tid < 192)  sMisc[tid] = bc1[tid - 128];
    else if (tid < 256)  sMisc[tid] = Wc2[tid - 192];
    const float bc2v = bc2[0];
    __syncthreads();

    const int warp = tid >> 5, lane = tid & 31;
    char* aPtr = sm + A_OFF + warp * 8192;
    const uint32_t aHi = smb + A_OFF + warp * 8192;

    // ldmatrix lane address components
    const int aRowL = ((lane >> 3) & 1) * 8 + (lane & 7);
    const int aCbL  = ((lane >> 4) & 1) * 16;
    const int bRowL = ((lane >> 4) & 1) * 8 + (lane & 7);
    const int bCbL  = ((lane >> 3) & 1) * 16;
    const int q2 = (lane & 3) * 2;     // col-pair base within ntile
    const int qr = lane >> 2;          // row-in-8

    const int estride = gridDim.x * 256;

    for (int e0 = (blockIdx.x * 8 + warp) * 32; e0 < E; e0 += estride) {
        // ---- per-edge meta (lane = edge slot) ----
        int e = e0 + lane;
        bool valid = e < E;
        int ec = valid ? e : (E - 1);
        int r = eidx[ec], cI = eidx[E + ec];
        float dx = coord[r * 3 + 0] - coord[cI * 3 + 0];
        float dy = coord[r * 3 + 1] - coord[cI * 3 + 1];
        float dz = coord[r * 3 + 2] - coord[cI * 3 + 2];
        float rad = valid ? (dx * dx + dy * dy + dz * dz) : 0.f;
        int rI = valid ? r : -1;

        float C[2][8][4];
        #pragma unroll
        for (int m = 0; m < 2; m++)
            #pragma unroll
            for (int n = 0; n < 8; n++)
                #pragma unroll
                for (int k = 0; k < 4; k++) C[m][n][k] = 0.f;

        // ================= GEMM1: [32,129] @ We1 -> C =================
        #pragma unroll
        for (int half = 0; half < 2; half++) {
            __syncwarp();
            // gather h[src] for this half into warp-private A (hi/lo planes)
            #pragma unroll
            for (int i = 0; i < 16; i++) {
                int edge = (i << 1) | (lane >> 4);
                int node = __shfl_sync(FULLM, half ? cI : r, edge);
                float4 v = *(const float4*)(h + (size_t)node * 64 + (lane & 15) * 4);
                uint32_t h0, l0, h1, l1;
                packhl(v.x, v.y, h0, l0);
                packhl(v.z, v.w, h1, l1);
                uint32_t off = (uint32_t)(edge * 128 + (((lane & 15) * 8) ^ ((edge & 7) << 4)));
                *(uint2*)(aPtr + off)        = make_uint2(h0, h1);
                *(uint2*)(aPtr + 4096 + off) = make_uint2(l0, l1);
            }
            __syncwarp();

            const uint32_t wB = smb + (half ? W1B_HI : W1A_HI);
            #pragma unroll
            for (int kt = 0; kt < 4; kt++) {
                uint32_t Ah[2][4], Al[2][4];
                #pragma unroll
                for (int m = 0; m < 2; m++) {
                    int ar = m * 16 + aRowL;
                    uint32_t ad = aHi + ar * 128 + ((kt * 32 + aCbL) ^ ((ar & 7) << 4));
                    ldsm4(Ah[m], ad);
                    ldsm4(Al[m], ad + 4096);
                }
                #pragma unroll
                for (int nt2 = 0; nt2 < 4; nt2++) {
                    uint32_t Bh[4], Bl[4];
                    int br = nt2 * 16 + bRowL;
                    uint32_t bd = wB + br * 128 + ((kt * 32 + bCbL) ^ ((br & 7) << 4));
                    ldsm4(Bh, bd);
                    ldsm4(Bl, bd + 8192);
                    #pragma unroll
                    for (int m = 0; m < 2; m++)
                        #pragma unroll
                        for (int p = 0; p < 2; p++) {
                            float* cc = C[m][nt2 * 2 + p];
                            mma_bf16(cc, Ah[m], Bh[2 * p], Bh[2 * p + 1]);
                            mma_bf16(cc, Ah[m], Bl[2 * p], Bl[2 * p + 1]);
                            mma_bf16(cc, Al[m], Bh[2 * p], Bh[2 * p + 1]);
                        }
                }
            }
        }

        // ---- epi1: bias + radial (fp32), relu, -> A2 register fragments ----
        uint32_t A2h[2][4][4], A2l[2][4][4];
        #pragma unroll
        for (int m = 0; m < 2; m++) {
            float rad0 = __shfl_sync(FULLM, rad, m * 16 + qr);
            float rad1 = __shfl_sync(FULLM, rad, m * 16 + 8 + qr);
            #pragma unroll
            for (int nt = 0; nt < 8; nt++) {
                int col0 = nt * 8 + q2;
                float2 bb = *(float2*)(sMisc + col0);
                float2 wr = *(float2*)(sMisc + 256 + col0);
                float c0 = fmaxf(C[m][nt][0] + bb.x + rad0 * wr.x, 0.f);
                float c1 = fmaxf(C[m][nt][1] + bb.y + rad0 * wr.y, 0.f);
                float c2 = fmaxf(C[m][nt][2] + bb.x + rad1 * wr.x, 0.f);
                float c3 = fmaxf(C[m][nt][3] + bb.y + rad1 * wr.y, 0.f);
                int kt = nt >> 1, o = (nt & 1) * 2;
                packhl(c0, c1, A2h[m][kt][o],     A2l[m][kt][o]);
                packhl(c2, c3, A2h[m][kt][o + 1], A2l[m][kt][o + 1]);
            }
        }

        // ================= GEMM2: hid @ We2 (A from regs) =================
        float C2[2][8][4];
        #pragma unroll
        for (int m = 0; m < 2; m++)
            #pragma unroll
            for (int n = 0; n < 8; n++)
                #pragma unroll
                for (int k = 0; k < 4; k++) C2[m][n][k] = 0.f;
        #pragma unroll
        for (int kt = 0; kt < 4; kt++) {
            #pragma unroll
            for (int nt2 = 0; nt2 < 4; nt2++) {
                uint32_t Bh[4], Bl[4];
                int br = nt2 * 16 + bRowL;
                uint32_t bd = smb + W2_HI + br * 128 + ((kt * 32 + bCbL) ^ ((br & 7) << 4));
                ldsm4(Bh, bd);
                ldsm4(Bl, bd + 8192);
                #pragma unroll
                for (int m = 0; m < 2; m++)
                    #pragma unroll
                    for (int p = 0; p < 2; p++) {
                        float* cc = C2[m][nt2 * 2 + p];
                        mma_bf16(cc, A2h[m][kt], Bh[2 * p], Bh[2 * p + 1]);
                        mma_bf16(cc, A2h[m][kt], Bl[2 * p], Bl[2 * p + 1]);
                        mma_bf16(cc, A2l[m][kt], Bh[2 * p], Bh[2 * p + 1]);
                    }
            }
        }

        // ---- epi2: feat = relu(C2 + be2); atomics to agg_h; -> A3 frags ----
        uint32_t A3h[2][4][4], A3l[2][4][4];
        #pragma unroll
        for (int m = 0; m < 2; m++) {
            int rr0 = __shfl_sync(FULLM, rI, m * 16 + qr);
            int rr1 = __shfl_sync(FULLM, rI, m * 16 + 8 + qr);
            #pragma unroll
            for (int nt = 0; nt < 8; nt++) {
                int col0 = nt * 8 + q2;
                float2 bb = *(float2*)(sMisc + 64 + col0);
                float f0 = fmaxf(C2[m][nt][0] + bb.x, 0.f);
                float f1 = fmaxf(C2[m][nt][1] + bb.y, 0.f);
                float f2 = fmaxf(C2[m][nt][2] + bb.x, 0.f);
                float f3 = fmaxf(C2[m][nt][3] + bb.y, 0.f);
                int kt = nt >> 1, o = (nt & 1) * 2;
                packhl(f0, f1, A3h[m][kt][o],     A3l[m][kt][o]);
                packhl(f2, f3, A3h[m][kt][o + 1], A3l[m][kt][o + 1]);
                if (rr0 >= 0)
                    atomicAdd((float2*)(g_agg_h + (size_t)rr0 * 64 + col0), make_float2(f0, f1));
                if (rr1 >= 0)
                    atomicAdd((float2*)(g_agg_h + (size_t)rr1 * 64 + col0), make_float2(f2, f3));
            }
        }

        // ================= GEMM3: feat @ Wc1 (A from regs) =================
        float C3[2][8][4];
        #pragma unroll
        for (int m = 0; m < 2; m++)
            #pragma unroll
            for (int n = 0; n < 8; n++)
                #pragma unroll
                for (int k = 0; k < 4; k++) C3[m][n][k] = 0.f;
        #pragma unroll
        for (int kt = 0; kt < 4; kt++) {
            #pragma unroll
            for (int nt2 = 0; nt2 < 4; nt2++) {
                uint32_t Bh[4], Bl[4];
                int br = nt2 * 16 + bRowL;
                uint32_t bd = smb + WC_HI + br * 128 + ((kt * 32 + bCbL) ^ ((br & 7) << 4));
                ldsm4(Bh, bd);
                ldsm4(Bl, bd + 8192);
                #pragma unroll
                for (int m = 0; m < 2; m++)
                    #pragma unroll
                    for (int p = 0; p < 2; p++) {
                        float* cc = C3[m][nt2 * 2 + p];
                        mma_bf16(cc, A3h[m][kt], Bh[2 * p], Bh[2 * p + 1]);
                        mma_bf16(cc, A3h[m][kt], Bl[2 * p], Bl[2 * p + 1]);
                        mma_bf16(cc, A3l[m][kt], Bh[2 * p], Bh[2 * p + 1]);
                    }
            }
        }

        // ---- epi3: gate = relu(C3 + bc1).wc2 + bc2; coord scatter ----
        #pragma unroll
        for (int m = 0; m < 2; m++) {
            float p0 = 0.f, p1 = 0.f;
            #pragma unroll
            for (int nt = 0; nt < 8; nt++) {
                int col0 = nt * 8 + q2;
                float2 bb = *(float2*)(sMisc + 128 + col0);
                float2 w2 = *(float2*)(sMisc + 192 + col0);
                p0 += fmaxf(C3[m][nt][0] + bb.x, 0.f) * w2.x
                    + fmaxf(C3[m][nt][1] + bb.y, 0.f) * w2.y;
                p1 += fmaxf(C3[m][nt][2] + bb.x, 0.f) * w2.x
                    + fmaxf(C3[m][nt][3] + bb.y, 0.f) * w2.y;
            }
            p0 += __shfl_xor_sync(FULLM, p0, 1);
            p0 += __shfl_xor_sync(FULLM, p0, 2);
            p1 += __shfl_xor_sync(FULLM, p1, 1);
            p1 += __shfl_xor_sync(FULLM, p1, 2);

            int row0 = m * 16 + qr, row1 = row0 + 8;
            float gx0 = __shfl_sync(FULLM, dx, row0), gy0 = __shfl_sync(FULLM, dy, row0),
                  gz0 = __shfl_sync(FULLM, dz, row0);
            float gx1 = __shfl_sync(FULLM, dx, row1), gy1 = __shfl_sync(FULLM, dy, row1),
                  gz1 = __shfl_sync(FULLM, dz, row1);
            int r0v = __shfl_sync(FULLM, rI, row0);
            int r1v = __shfl_sync(FULLM, rI, row1);

            if ((lane & 3) == 0) {
                if (r0v >= 0) {
                    float gt = p0 + bc2v;
                    atomicAdd(&g_sum4[r0v], make_float4(
                        fminf(fmaxf(gx0 * gt, -100.f), 100.f),
                        fminf(fmaxf(gy0 * gt, -100.f), 100.f),
                        fminf(fmaxf(gz0 * gt, -100.f), 100.f), 1.f));
                }
                if (r1v >= 0) {
                    float gt = p1 + bc2v;
                    atomicAdd(&g_sum4[r1v], make_float4(
                        fminf(fmaxf(gx1 * gt, -100.f), 100.f),
                        fminf(fmaxf(gy1 * gt, -100.f), 100.f),
                        fminf(fmaxf(gz1 * gt, -100.f), 100.f), 1.f));
                }
            }
        }
    }
}

// ===========================================================================
// FFMA2 helpers (node kernel, R2-proven)
// ===========================================================================
__device__ __forceinline__ u64 pk2(float x) {
    u64 r; asm("mov.b64 %0,{%1,%1};" : "=l"(r) : "f"(x)); return r;
}
__device__ __forceinline__ void fma2(u64 &d, u64 a, u64 b) {
    asm("fma.rn.f32x2 %0,%1,%2,%0;" : "+l"(d) : "l"(a), "l"(b));
}
__device__ __forceinline__ float2 up2(u64 v) {
    float2 f; asm("mov.b64 {%0,%1},%2;" : "=f"(f.x), "=f"(f.y) : "l"(v)); return f;
}
__device__ __forceinline__ void step2(u64 A[2][4], float x0, float x1, const float* w) {
    ulonglong2 w01 = *(const ulonglong2*)(w);
    ulonglong2 w23 = *(const ulonglong2*)(w + 4);
    u64 p0 = pk2(x0), p1 = pk2(x1);
    fma2(A[0][0], p0, w01.x); fma2(A[0][1], p0, w01.y);
    fma2(A[0][2], p0, w23.x); fma2(A[0][3], p0, w23.y);
    fma2(A[1][0], p1, w01.x); fma2(A[1][1], p1, w01.y);
    fma2(A[1][2], p1, w23.x); fma2(A[1][3], p1, w23.y);
}
__device__ __forceinline__ void initA(u64 A[2][4], const float* b) {
    ulonglong2 b01 = *(const ulonglong2*)b;
    ulonglong2 b23 = *(const ulonglong2*)(b + 4);
    A[0][0] = A[1][0] = b01.x; A[0][1] = A[1][1] = b01.y;
    A[0][2] = A[1][2] = b23.x; A[0][3] = A[1][3] = b23.y;
}
template<int K>
__device__ __forceinline__ void gemm_rows(u64 A[2][4], const float* r0, const float* r1,
                                          const float* Wb, int j0) {
    #pragma unroll 2
    for (int k0 = 0; k0 < K; k0 += 4) {
        float4 a0 = *(const float4*)(r0 + k0);
        float4 a1 = *(const float4*)(r1 + k0);
        step2(A, a0.x, a1.x, Wb + (k0 + 0) * 64 + j0);
        step2(A, a0.y, a1.y, Wb + (k0 + 1) * 64 + j0);
        step2(A, a0.z, a1.z, Wb + (k0 + 2) * 64 + j0);
        step2(A, a0.w, a1.w, Wb + (k0 + 3) * 64 + j0);
    }
}
__device__ __forceinline__ void relu_store2(u64 A[2][4], float* d0, float* d1, int j0) {
    #pragma unroll
    for (int p = 0; p < 4; p++) {
        float2 v0 = up2(A[0][p]);
        v0.x = fmaxf(v0.x, 0.f); v0.y = fmaxf(v0.y, 0.f);
        *(float2*)(d0 + j0 + 2 * p) = v0;
        float2 v1 = up2(A[1][p]);
        v1.x = fmaxf(v1.x, 0.f); v1.y = fmaxf(v1.y, 0.f);
        *(float2*)(d1 + j0 + 2 * p) = v1;
    }
}

// ---------------------------------------------------------------------------
__global__ void zero_kernel(int n) {
    int total = n * 17;
    int stride = gridDim.x * blockDim.x;
    float4 z = make_float4(0.f, 0.f, 0.f, 0.f);
    for (int i = blockIdx.x * blockDim.x + threadIdx.x; i < total; i += stride) {
        if (i < n * 16) ((float4*)g_agg_h)[i] = z;
        else            g_sum4[i - n * 16] = z;
    }
}

// ---------------------------------------------------------------------------
#define TPB 256
#define NLD 200
__global__ __launch_bounds__(TPB, 2) void node_kernel(
    const float* __restrict__ h,
    const float* __restrict__ Wn1, const float* __restrict__ bn1,
    const float* __restrict__ Wn2, const float* __restrict__ bn2,
    float* __restrict__ out_h, int N)
{
    extern __shared__ float smn[];
    float* sWn1 = smn;
    float* sWn2 = sWn1 + 128 * 64;
    float* sB   = sWn2 + 64 * 64;
    float* sAct = sB + 128;

    const int tid = threadIdx.x;
    for (int i = tid; i < 128 * 64; i += TPB) sWn1[i] = Wn1[i];
    for (int i = tid; i < 64 * 64; i += TPB)  sWn2[i] = Wn2[i];
    if (tid < 64)        sB[tid] = bn1[tid];
    else if (tid < 128)  sB[tid] = bn2[tid - 64];
    __syncthreads();

    const int warp = tid >> 5, lane = tid & 31;
    const int eq = lane >> 3, jg = lane & 7, j0 = jg * 8;
    float* W = sAct + warp * (8 * NLD);

    const int ngroups = (N + 7) >> 3;
    const int nwarps = gridDim.x * (TPB / 32);

    for (int g = blockIdx.x * (TPB / 32) + warp; g < ngroups; g += nwarps) {
        const int nbase = g * 8;
        #pragma unroll
        for (int i = 0; i < 8; i++) {
            int node = nbase + i;
            if (node >= N) continue;
            const float* src = (lane < 16) ? (h + (size_t)node * 64 + lane * 4)
                                           : (g_agg_h + (size_t)node * 64 + (lane - 16) * 4);
            float4 v = *(const float4*)src;
            float* dst = (lane < 16) ? (W + i * NLD + lane * 4)
                                     : (W + i * NLD + 64 + (lane - 16) * 4);
            *(float4*)dst = v;
        }
        __syncwarp();

        float* r0 = W + (2 * eq) * NLD;
        float* r1 = r0 + NLD;
        const int n0 = nbase + 2 * eq, n1 = n0 + 1;

        u64 A[2][4];
        initA(A, sB + j0);
        gemm_rows<128>(A, r0, r1, sWn1, j0);
        relu_store2(A, r0 + 128, r1 + 128, j0);
        __syncwarp();

        u64 O[2][4];
        initA(O, sB + 64 + j0);
        gemm_rows<64>(O, r0 + 128, r1 + 128, sWn2, j0);

        if (n0 < N) {
            float2 o0 = up2(O[0][0]), o1 = up2(O[0][1]), o2 = up2(O[0][2]), o3 = up2(O[0][3]);
            float4 lo = make_float4(o0.x + r0[j0+0], o0.y + r0[j0+1], o1.x + r0[j0+2], o1.y + r0[j0+3]);
            float4 hi = make_float4(o2.x + r0[j0+4], o2.y + r0[j0+5], o3.x + r0[j0+6], o3.y + r0[j0+7]);
            *(float4*)(out_h + (size_t)n0 * 64 + j0)     = lo;
            *(float4*)(out_h + (size_t)n0 * 64 + j0 + 4) = hi;
        }
        if (n1 < N) {
            float2 o0 = up2(O[1][0]), o1 = up2(O[1][1]), o2 = up2(O[1][2]), o3 = up2(O[1][3]);
            float4 lo = make_float4(o0.x + r1[j0+0], o0.y + r1[j0+1], o1.x + r1[j0+2], o1.y + r1[j0+3]);
            float4 hi = make_float4(o2.x + r1[j0+4], o2.y + r1[j0+5], o3.x + r1[j0+6], o3.y + r1[j0+7]);
            *(float4*)(out_h + (size_t)n1 * 64 + j0)     = lo;
            *(float4*)(out_h + (size_t)n1 * 64 + j0 + 4) = hi;
        }
    }
}

// ---------------------------------------------------------------------------
__global__ void coord_kernel(const float* __restrict__ coord,
                             const float* __restrict__ vel,
                             float* __restrict__ out_coord,
                             float* __restrict__ out_v, int N)
{
    int i = blockIdx.x * blockDim.x + threadIdx.x;
    if (i < N) {
        float4 s = g_sum4[i];
        float c = s.w;
        float invc = (c > 0.f) ? (1.f / fmaxf(c, 1.f)) : 0.f;
        float vx = vel[i * 3 + 0] + s.x * invc * 0.125f;
        float vy = vel[i * 3 + 1] + s.y * invc * 0.125f;
        float vz = vel[i * 3 + 2] + s.z * invc * 0.125f;
        out_v[i * 3 + 0] = vx;
        out_v[i * 3 + 1] = vy;
        out_v[i * 3 + 2] = vz;
        out_coord[i * 3 + 0] = coord[i * 3 + 0] + vx * 0.125f;
        out_coord[i * 3 + 1] = coord[i * 3 + 1] + vy * 0.125f;
        out_coord[i * 3 + 2] = coord[i * 3 + 2] + vz * 0.125f;
    }
}

// ---------------------------------------------------------------------------
extern "C" void kernel_launch(void* const* d_in, const int* in_sizes, int n_in,
                              void* d_out, int out_size)
{
    const float* h     = (const float*)d_in[0];
    const float* coord = (const float*)d_in[1];
    const float* vel   = (const float*)d_in[2];
    const int*   eidx  = (const int*)d_in[4];
    const float* We1 = (const float*)d_in[5];
    const float* be1 = (const float*)d_in[6];
    const float* We2 = (const float*)d_in[7];
    const float* be2 = (const float*)d_in[8];
    const float* Wn1 = (const float*)d_in[9];
    const float* bn1 = (const float*)d_in[10];
    const float* Wn2 = (const float*)d_in[11];
    const float* bn2 = (const float*)d_in[12];
    const float* Wc1 = (const float*)d_in[13];
    const float* bc1 = (const float*)d_in[14];
    const float* Wc2 = (const float*)d_in[15];
    const float* bc2 = (const float*)d_in[16];

    const int N = in_sizes[0] / 64;
    const int E = in_sizes[4] / 2;

    float* out       = (float*)d_out;
    float* out_h     = out;
    float* out_coord = out + (size_t)N * 64;
    float* out_v     = out_coord + (size_t)N * 3;

    const size_t smN = (size_t)(128*64 + 64*64 + 128 + 8*8*NLD) * sizeof(float);

    cudaFuncSetAttribute(edge_mma_kernel, cudaFuncAttributeMaxDynamicSharedMemorySize, SMEM_E);
    cudaFuncSetAttribute(node_kernel, cudaFuncAttributeMaxDynamicSharedMemorySize, (int)smN);

    zero_kernel<<<512, 256>>>(N);
    edge_mma_kernel<<<148, 256, SMEM_E>>>(h, coord, eidx, E,
                                          We1, be1, We2, be2, Wc1, bc1, Wc2, bc2);
    node_kernel<<<296, TPB, smN>>>(h, Wn1, bn1, Wn2, bn2, out_h, N);
    coord_kernel<<<(N + 255) / 256, 256>>>(coord, vel, out_coord, out_v, N);
}

// round 5
// speedup vs baseline: 11.2812x; 1.2025x over previous
#include <cuda_runtime.h>
#include <cuda_bf16.h>
#include <cstdint>

typedef unsigned long long u64;
#define FULLM 0xffffffffu

#define NMAX 50048
__device__ float  g_agg_h[(size_t)NMAX * 64];
__device__ float4 g_sum4[NMAX];

// ===========================================================================
// common helpers
// ===========================================================================
__device__ __forceinline__ uint32_t smem_to_u32(const void* p) {
    uint32_t a;
    asm("{ .reg .u64 t; cvta.to.shared.u64 t, %1; cvt.u32.u64 %0, t; }" : "=r"(a) : "l"(p));
    return a;
}
__device__ __forceinline__ void ldsm4(uint32_t r[4], uint32_t addr) {
    asm volatile("ldmatrix.sync.aligned.m8n8.x4.shared.b16 {%0,%1,%2,%3}, [%4];"
        : "=r"(r[0]), "=r"(r[1]), "=r"(r[2]), "=r"(r[3]) : "r"(addr));
}
__device__ __forceinline__ void mma_bf16(float c[4], const uint32_t a[4],
                                         uint32_t b0, uint32_t b1) {
    asm volatile("mma.sync.aligned.m16n8k16.row.col.f32.bf16.bf16.f32 "
        "{%0,%1,%2,%3},{%4,%5,%6,%7},{%8,%9},{%0,%1,%2,%3};"
        : "+f"(c[0]), "+f"(c[1]), "+f"(c[2]), "+f"(c[3])
        : "r"(a[0]), "r"(a[1]), "r"(a[2]), "r"(a[3]), "r"(b0), "r"(b1));
}
__device__ __forceinline__ void packhl(float a, float b, uint32_t &hi, uint32_t &lo) {
    __nv_bfloat162 hh = __floats2bfloat162_rn(a, b);
    float ra = a - __bfloat162float(hh.x);
    float rb = b - __bfloat162float(hh.y);
    __nv_bfloat162 ll = __floats2bfloat162_rn(ra, rb);
    hi = *(uint32_t*)&hh;
    lo = *(uint32_t*)&ll;
}
__device__ __forceinline__ void putw(char* sm, int plane, int j, int k, float x) {
    __nv_bfloat16 hb = __float2bfloat16(x);
    __nv_bfloat16 lb = __float2bfloat16(x - __bfloat162float(hb));
    uint32_t off = (uint32_t)(j * 128 + ((k * 2) ^ ((j & 7) << 4)));
    *(__nv_bfloat16*)(sm + plane + off) = hb;
    *(__nv_bfloat16*)(sm + plane + 8192 + off) = lb;
}

// ===========================================================================
// Edge kernel smem layout
// ===========================================================================
#define ETPB 320
#define EWARPS 10
#define W1A_HI   0
#define W1B_HI   16384
#define W2_HI    32768
#define WC_HI    49152
#define A_OFF    65536                       // per warp 8192 (hi|lo 4096)
#define MISC_OFF (A_OFF + EWARPS * 8192)     // fp32: be1|be2|bc1|wc2|w1rad
#define SMEM_E   (MISC_OFF + 1280)

__global__ __launch_bounds__(ETPB, 1) void edge_mma_kernel(
    const float* __restrict__ h, const float* __restrict__ coord,
    const int* __restrict__ eidx, int E,
    const float* __restrict__ We1, const float* __restrict__ be1,
    const float* __restrict__ We2, const float* __restrict__ be2,
    const float* __restrict__ Wc1, const float* __restrict__ bc1,
    const float* __restrict__ Wc2, const float* __restrict__ bc2)
{
    extern __shared__ char sm[];
    const uint32_t smb = smem_to_u32(sm);
    const int tid = threadIdx.x;
    float* sMisc = (float*)(sm + MISC_OFF);

    for (int i = tid; i < 129 * 64; i += ETPB) {
        int k = i >> 6, j = i & 63;
        float x = We1[i];
        if (k < 128) putw(sm, (k < 64) ? W1A_HI : W1B_HI, j, k & 63, x);
        else         sMisc[256 + j] = x;
    }
    for (int i = tid; i < 64 * 64; i += ETPB) {
        int k = i >> 6, j = i & 63;
        putw(sm, W2_HI, j, k, We2[i]);
        putw(sm, WC_HI, j, k, Wc1[i]);
    }
    if (tid < 64)        sMisc[tid] = be1[tid];
    else if (tid < 128)  sMisc[tid] = be2[tid - 64];
    else if (tid < 192)  sMisc[tid] = bc1[tid - 128];
    else if (tid < 256)  sMisc[tid] = Wc2[tid - 192];
    const float bc2v = bc2[0];
    __syncthreads();

    const int warp = tid >> 5, lane = tid & 31;
    char* aPtr = sm + A_OFF + warp * 8192;
    const uint32_t aHi = smb + A_OFF + warp * 8192;

    const int aRowL = ((lane >> 3) & 1) * 8 + (lane & 7);
    const int aCbL  = ((lane >> 4) & 1) * 16;
    const int bRowL = ((lane >> 4) & 1) * 8 + (lane & 7);
    const int bCbL  = ((lane >> 3) & 1) * 16;
    const int q2 = (lane & 3) * 2;
    const int qr = lane >> 2;

    const int estride = gridDim.x * ETPB;

    for (int e0 = (blockIdx.x * EWARPS + warp) * 32; e0 < E; e0 += estride) {
        int e = e0 + lane;
        bool valid = e < E;
        int ec = valid ? e : (E - 1);
        int r = eidx[ec], cI = eidx[E + ec];
        float dx = coord[r * 3 + 0] - coord[cI * 3 + 0];
        float dy = coord[r * 3 + 1] - coord[cI * 3 + 1];
        float dz = coord[r * 3 + 2] - coord[cI * 3 + 2];
        float rad = valid ? (dx * dx + dy * dy + dz * dz) : 0.f;
        int rI = valid ? r : -1;

        float C[2][8][4];
        #pragma unroll
        for (int m = 0; m < 2; m++)
            #pragma unroll
            for (int n = 0; n < 8; n++)
                #pragma unroll
                for (int k = 0; k < 4; k++) C[m][n][k] = 0.f;

        // ================= GEMM1 =================
        #pragma unroll
        for (int half = 0; half < 2; half++) {
            __syncwarp();
            #pragma unroll
            for (int i = 0; i < 16; i++) {
                int edge = (i << 1) | (lane >> 4);
                int node = __shfl_sync(FULLM, half ? cI : r, edge);
                float4 v = *(const float4*)(h + (size_t)node * 64 + (lane & 15) * 4);
                uint32_t h0, l0, h1, l1;
                packhl(v.x, v.y, h0, l0);
                packhl(v.z, v.w, h1, l1);
                uint32_t off = (uint32_t)(edge * 128 + (((lane & 15) * 8) ^ ((edge & 7) << 4)));
                *(uint2*)(aPtr + off)        = make_uint2(h0, h1);
                *(uint2*)(aPtr + 4096 + off) = make_uint2(l0, l1);
            }
            __syncwarp();

            const uint32_t wB = smb + (half ? W1B_HI : W1A_HI);
            #pragma unroll
            for (int kt = 0; kt < 4; kt++) {
                uint32_t Ah[2][4], Al[2][4];
                #pragma unroll
                for (int m = 0; m < 2; m++) {
                    int ar = m * 16 + aRowL;
                    uint32_t ad = aHi + ar * 128 + ((kt * 32 + aCbL) ^ ((ar & 7) << 4));
                    ldsm4(Ah[m], ad);
                    ldsm4(Al[m], ad + 4096);
                }
                #pragma unroll
                for (int nt2 = 0; nt2 < 4; nt2++) {
                    uint32_t Bh[4], Bl[4];
                    int br = nt2 * 16 + bRowL;
                    uint32_t bd = wB + br * 128 + ((kt * 32 + bCbL) ^ ((br & 7) << 4));
                    ldsm4(Bh, bd);
                    ldsm4(Bl, bd + 8192);
                    #pragma unroll
                    for (int m = 0; m < 2; m++)
                        #pragma unroll
                        for (int p = 0; p < 2; p++) {
                            float* cc = C[m][nt2 * 2 + p];
                            mma_bf16(cc, Ah[m], Bh[2 * p], Bh[2 * p + 1]);
                            mma_bf16(cc, Ah[m], Bl[2 * p], Bl[2 * p + 1]);
                            mma_bf16(cc, Al[m], Bh[2 * p], Bh[2 * p + 1]);
                        }
                }
            }
        }

        // ---- epi1 ----
        uint32_t A2h[2][4][4], A2l[2][4][4];
        #pragma unroll
        for (int m = 0; m < 2; m++) {
            float rad0 = __shfl_sync(FULLM, rad, m * 16 + qr);
            float rad1 = __shfl_sync(FULLM, rad, m * 16 + 8 + qr);
            #pragma unroll
            for (int nt = 0; nt < 8; nt++) {
                int col0 = nt * 8 + q2;
                float2 bb = *(float2*)(sMisc + col0);
                float2 wr = *(float2*)(sMisc + 256 + col0);
                float c0 = fmaxf(C[m][nt][0] + bb.x + rad0 * wr.x, 0.f);
                float c1 = fmaxf(C[m][nt][1] + bb.y + rad0 * wr.y, 0.f);
                float c2 = fmaxf(C[m][nt][2] + bb.x + rad1 * wr.x, 0.f);
                float c3 = fmaxf(C[m][nt][3] + bb.y + rad1 * wr.y, 0.f);
                int kt = nt >> 1, o = (nt & 1) * 2;
                packhl(c0, c1, A2h[m][kt][o],     A2l[m][kt][o]);
                packhl(c2, c3, A2h[m][kt][o + 1], A2l[m][kt][o + 1]);
            }
        }

        // ================= GEMM2 =================
        float C2[2][8][4];
        #pragma unroll
        for (int m = 0; m < 2; m++)
            #pragma unroll
            for (int n = 0; n < 8; n++)
                #pragma unroll
                for (int k = 0; k < 4; k++) C2[m][n][k] = 0.f;
        #pragma unroll
        for (int kt = 0; kt < 4; kt++) {
            #pragma unroll
            for (int nt2 = 0; nt2 < 4; nt2++) {
                uint32_t Bh[4], Bl[4];
                int br = nt2 * 16 + bRowL;
                uint32_t bd = smb + W2_HI + br * 128 + ((kt * 32 + bCbL) ^ ((br & 7) << 4));
                ldsm4(Bh, bd);
                ldsm4(Bl, bd + 8192);
                #pragma unroll
                for (int m = 0; m < 2; m++)
                    #pragma unroll
                    for (int p = 0; p < 2; p++) {
                        float* cc = C2[m][nt2 * 2 + p];
                        mma_bf16(cc, A2h[m][kt], Bh[2 * p], Bh[2 * p + 1]);
                        mma_bf16(cc, A2h[m][kt], Bl[2 * p], Bl[2 * p + 1]);
                        mma_bf16(cc, A2l[m][kt], Bh[2 * p], Bh[2 * p + 1]);
                    }
            }
        }

        // ---- epi2 ----
        uint32_t A3h[2][4][4], A3l[2][4][4];
        #pragma unroll
        for (int m = 0; m < 2; m++) {
            int rr0 = __shfl_sync(FULLM, rI, m * 16 + qr);
            int rr1 = __shfl_sync(FULLM, rI, m * 16 + 8 + qr);
            #pragma unroll
            for (int nt = 0; nt < 8; nt++) {
                int col0 = nt * 8 + q2;
                float2 bb = *(float2*)(sMisc + 64 + col0);
                float f0 = fmaxf(C2[m][nt][0] + bb.x, 0.f);
                float f1 = fmaxf(C2[m][nt][1] + bb.y, 0.f);
                float f2 = fmaxf(C2[m][nt][2] + bb.x, 0.f);
                float f3 = fmaxf(C2[m][nt][3] + bb.y, 0.f);
                int kt = nt >> 1, o = (nt & 1) * 2;
                packhl(f0, f1, A3h[m][kt][o],     A3l[m][kt][o]);
                packhl(f2, f3, A3h[m][kt][o + 1], A3l[m][kt][o + 1]);
                if (rr0 >= 0)
                    atomicAdd((float2*)(g_agg_h + (size_t)rr0 * 64 + col0), make_float2(f0, f1));
                if (rr1 >= 0)
                    atomicAdd((float2*)(g_agg_h + (size_t)rr1 * 64 + col0), make_float2(f2, f3));
            }
        }

        // ================= GEMM3 =================
        float C3[2][8][4];
        #pragma unroll
        for (int m = 0; m < 2; m++)
            #pragma unroll
            for (int n = 0; n < 8; n++)
                #pragma unroll
                for (int k = 0; k < 4; k++) C3[m][n][k] = 0.f;
        #pragma unroll
        for (int kt = 0; kt < 4; kt++) {
            #pragma unroll
            for (int nt2 = 0; nt2 < 4; nt2++) {
                uint32_t Bh[4], Bl[4];
                int br = nt2 * 16 + bRowL;
                uint32_t bd = smb + WC_HI + br * 128 + ((kt * 32 + bCbL) ^ ((br & 7) << 4));
                ldsm4(Bh, bd);
                ldsm4(Bl, bd + 8192);
                #pragma unroll
                for (int m = 0; m < 2; m++)
                    #pragma unroll
                    for (int p = 0; p < 2; p++) {
                        float* cc = C3[m][nt2 * 2 + p];
                        mma_bf16(cc, A3h[m][kt], Bh[2 * p], Bh[2 * p + 1]);
                        mma_bf16(cc, A3h[m][kt], Bl[2 * p], Bl[2 * p + 1]);
                        mma_bf16(cc, A3l[m][kt], Bh[2 * p], Bh[2 * p + 1]);
                    }
            }
        }

        // ---- epi3 ----
        #pragma unroll
        for (int m = 0; m < 2; m++) {
            float p0 = 0.f, p1 = 0.f;
            #pragma unroll
            for (int nt = 0; nt < 8; nt++) {
                int col0 = nt * 8 + q2;
                float2 bb = *(float2*)(sMisc + 128 + col0);
                float2 w2 = *(float2*)(sMisc + 192 + col0);
                p0 += fmaxf(C3[m][nt][0] + bb.x, 0.f) * w2.x
                    + fmaxf(C3[m][nt][1] + bb.y, 0.f) * w2.y;
                p1 += fmaxf(C3[m][nt][2] + bb.x, 0.f) * w2.x
                    + fmaxf(C3[m][nt][3] + bb.y, 0.f) * w2.y;
            }
            p0 += __shfl_xor_sync(FULLM, p0, 1);
            p0 += __shfl_xor_sync(FULLM, p0, 2);
            p1 += __shfl_xor_sync(FULLM, p1, 1);
            p1 += __shfl_xor_sync(FULLM, p1, 2);

            int row0 = m * 16 + qr, row1 = row0 + 8;
            float gx0 = __shfl_sync(FULLM, dx, row0), gy0 = __shfl_sync(FULLM, dy, row0),
                  gz0 = __shfl_sync(FULLM, dz, row0);
            float gx1 = __shfl_sync(FULLM, dx, row1), gy1 = __shfl_sync(FULLM, dy, row1),
                  gz1 = __shfl_sync(FULLM, dz, row1);
            int r0v = __shfl_sync(FULLM, rI, row0);
            int r1v = __shfl_sync(FULLM, rI, row1);

            if ((lane & 3) == 0) {
                if (r0v >= 0) {
                    float gt = p0 + bc2v;
                    atomicAdd(&g_sum4[r0v], make_float4(
                        fminf(fmaxf(gx0 * gt, -100.f), 100.f),
                        fminf(fmaxf(gy0 * gt, -100.f), 100.f),
                        fminf(fmaxf(gz0 * gt, -100.f), 100.f), 1.f));
                }
                if (r1v >= 0) {
                    float gt = p1 + bc2v;
                    atomicAdd(&g_sum4[r1v], make_float4(
                        fminf(fmaxf(gx1 * gt, -100.f), 100.f),
                        fminf(fmaxf(gy1 * gt, -100.f), 100.f),
                        fminf(fmaxf(gz1 * gt, -100.f), 100.f), 1.f));
                }
            }
        }
    }
}

// ===========================================================================
// Node kernel: bf16x3 HMMA, warp = 32 nodes x 64 outs; coord fused at head
// ===========================================================================
#define NW1A 0
#define NW1B 16384
#define NW2  32768
#define NMISC 49152
#define NA_OFF 50176
#define SMEM_N (NA_OFF + 8 * 8192)

__global__ __launch_bounds__(256, 1) void node_mma_kernel(
    const float* __restrict__ h,
    const float* __restrict__ Wn1, const float* __restrict__ bn1,
    const float* __restrict__ Wn2, const float* __restrict__ bn2,
    const float* __restrict__ coord, const float* __restrict__ vel,
    float* __restrict__ out_h, float* __restrict__ out_coord,
    float* __restrict__ out_v, int N)
{
    extern __shared__ char sm[];
    const uint32_t smb = smem_to_u32(sm);
    const int tid = threadIdx.x;
    float* sMisc = (float*)(sm + NMISC);

    // ---- fused coord/velocity update ----
    for (int i = blockIdx.x * 256 + tid; i < N; i += gridDim.x * 256) {
        float4 s = g_sum4[i];
        float c = s.w;
        float invc = (c > 0.f) ? (1.f / fmaxf(c, 1.f)) : 0.f;
        float vx = vel[i * 3 + 0] + s.x * invc * 0.125f;
        float vy = vel[i * 3 + 1] + s.y * invc * 0.125f;
        float vz = vel[i * 3 + 2] + s.z * invc * 0.125f;
        out_v[i * 3 + 0] = vx;
        out_v[i * 3 + 1] = vy;
        out_v[i * 3 + 2] = vz;
        out_coord[i * 3 + 0] = coord[i * 3 + 0] + vx * 0.125f;
        out_coord[i * 3 + 1] = coord[i * 3 + 1] + vy * 0.125f;
        out_coord[i * 3 + 2] = coord[i * 3 + 2] + vz * 0.125f;
    }

    // ---- stage weights ----
    for (int i = tid; i < 128 * 64; i += 256) {
        int k = i >> 6, j = i & 63;
        putw(sm, (k < 64) ? NW1A : NW1B, j, k & 63, Wn1[i]);
    }
    for (int i = tid; i < 64 * 64; i += 256) {
        int k = i >> 6, j = i & 63;
        putw(sm, NW2, j, k, Wn2[i]);
    }
    if (tid < 64)        sMisc[tid] = bn1[tid];
    else if (tid < 128)  sMisc[tid] = bn2[tid - 64];
    __syncthreads();

    const int warp = tid >> 5, lane = tid & 31;
    char* aPtr = sm + NA_OFF + warp * 8192;
    const uint32_t aHi = smb + NA_OFF + warp * 8192;

    const int aRowL = ((lane >> 3) & 1) * 8 + (lane & 7);
    const int aCbL  = ((lane >> 4) & 1) * 16;
    const int bRowL = ((lane >> 4) & 1) * 8 + (lane & 7);
    const int bCbL  = ((lane >> 3) & 1) * 16;
    const int q2 = (lane & 3) * 2;
    const int qr = lane >> 2;

    const int ntiles = (N + 31) >> 5;

    for (int t = blockIdx.x * 8 + warp; t < ntiles; t += gridDim.x * 8) {
        const int nbase = t << 5;

        float C[2][8][4];
        #pragma unroll
        for (int m = 0; m < 2; m++)
            #pragma unroll
            for (int n = 0; n < 8; n++)
                #pragma unroll
                for (int k = 0; k < 4; k++) C[m][n][k] = 0.f;

        // GEMM1: [h || agg_h] @ Wn1
        #pragma unroll
        for (int half = 0; half < 2; half++) {
            __syncwarp();
            const float* src = half ? g_agg_h : h;
            #pragma unroll
            for (int i = 0; i < 16; i++) {
                int row = (i << 1) | (lane >> 4);
                int node = nbase + row;
                if (node >= N) node = N - 1;
                float4 v = *(const float4*)(src + (size_t)node * 64 + (lane & 15) * 4);
                uint32_t h0, l0, h1, l1;
                packhl(v.x, v.y, h0, l0);
                packhl(v.z, v.w, h1, l1);
                uint32_t off = (uint32_t)(row * 128 + (((lane & 15) * 8) ^ ((row & 7) << 4)));
                *(uint2*)(aPtr + off)        = make_uint2(h0, h1);
                *(uint2*)(aPtr + 4096 + off) = make_uint2(l0, l1);
            }
            __syncwarp();

            const uint32_t wB = smb + (half ? NW1B : NW1A);
            #pragma unroll
            for (int kt = 0; kt < 4; kt++) {
                uint32_t Ah[2][4], Al[2][4];
                #pragma unroll
                for (int m = 0; m < 2; m++) {
                    int ar = m * 16 + aRowL;
                    uint32_t ad = aHi + ar * 128 + ((kt * 32 + aCbL) ^ ((ar & 7) << 4));
                    ldsm4(Ah[m], ad);
                    ldsm4(Al[m], ad + 4096);
                }
                #pragma unroll
                for (int nt2 = 0; nt2 < 4; nt2++) {
                    uint32_t Bh[4], Bl[4];
                    int br = nt2 * 16 + bRowL;
                    uint32_t bd = wB + br * 128 + ((kt * 32 + bCbL) ^ ((br & 7) << 4));
                    ldsm4(Bh, bd);
                    ldsm4(Bl, bd + 8192);
                    #pragma unroll
                    for (int m = 0; m < 2; m++)
                        #pragma unroll
                        for (int p = 0; p < 2; p++) {
                            float* cc = C[m][nt2 * 2 + p];
                            mma_bf16(cc, Ah[m], Bh[2 * p], Bh[2 * p + 1]);
                            mma_bf16(cc, Ah[m], Bl[2 * p], Bl[2 * p + 1]);
                            mma_bf16(cc, Al[m], Bh[2 * p], Bh[2 * p + 1]);
                        }
                }
            }
        }

        // epi1: bias + relu -> A2 frags
        uint32_t A2h[2][4][4], A2l[2][4][4];
        #pragma unroll
        for (int m = 0; m < 2; m++) {
            #pragma unroll
            for (int nt = 0; nt < 8; nt++) {
                int col0 = nt * 8 + q2;
                float2 bb = *(float2*)(sMisc + col0);
                float c0 = fmaxf(C[m][nt][0] + bb.x, 0.f);
                float c1 = fmaxf(C[m][nt][1] + bb.y, 0.f);
                float c2 = fmaxf(C[m][nt][2] + bb.x, 0.f);
                float c3 = fmaxf(C[m][nt][3] + bb.y, 0.f);
                int kt = nt >> 1, o = (nt & 1) * 2;
                packhl(c0, c1, A2h[m][kt][o],     A2l[m][kt][o]);
                packhl(c2, c3, A2h[m][kt][o + 1], A2l[m][kt][o + 1]);
            }
        }

        // GEMM2: hid @ Wn2
        float C2[2][8][4];
        #pragma unroll
        for (int m = 0; m < 2; m++)
            #pragma unroll
            for (int n = 0; n < 8; n++)
                #pragma unroll
                for (int k = 0; k < 4; k++) C2[m][n][k] = 0.f;
        #pragma unroll
        for (int kt = 0; kt < 4; kt++) {
            #pragma unroll
            for (int nt2 = 0; nt2 < 4; nt2++) {
                uint32_t Bh[4], Bl[4];
                int br = nt2 * 16 + bRowL;
                uint32_t bd = smb + NW2 + br * 128 + ((kt * 32 + bCbL) ^ ((br & 7) << 4));
                ldsm4(Bh, bd);
                ldsm4(Bl, bd + 8192);
                #pragma unroll
                for (int m = 0; m < 2; m++)
                    #pragma unroll
                    for (int p = 0; p < 2; p++) {
                        float* cc = C2[m][nt2 * 2 + p];
                        mma_bf16(cc, A2h[m][kt], Bh[2 * p], Bh[2 * p + 1]);
                        mma_bf16(cc, A2h[m][kt], Bl[2 * p], Bl[2 * p + 1]);
                        mma_bf16(cc, A2l[m][kt], Bh[2 * p], Bh[2 * p + 1]);
                    }
            }
        }

        // epi2: + bn2 + residual h -> out_h
        #pragma unroll
        for (int m = 0; m < 2; m++) {
            int row0 = nbase + m * 16 + qr;
            int row1 = row0 + 8;
            bool v0 = row0 < N, v1 = row1 < N;
            #pragma unroll
            for (int nt = 0; nt < 8; nt++) {
                int col0 = nt * 8 + q2;
                float2 bb = *(float2*)(sMisc + 64 + col0);
                if (v0) {
                    float2 rs = *(const float2*)(h + (size_t)row0 * 64 + col0);
                    float2 o = make_float2(C2[m][nt][0] + bb.x + rs.x,
                                           C2[m][nt][1] + bb.y + rs.y);
                    *(float2*)(out_h + (size_t)row0 * 64 + col0) = o;
                }
                if (v1) {
                    float2 rs = *(const float2*)(h + (size_t)row1 * 64 + col0);
                    float2 o = make_float2(C2[m][nt][2] + bb.x + rs.x,
                                           C2[m][nt][3] + bb.y + rs.y);
                    *(float2*)(out_h + (size_t)row1 * 64 + col0) = o;
                }
            }
        }
    }
}

// ---------------------------------------------------------------------------
__global__ void zero_kernel(int n) {
    int total = n * 17;
    int stride = gridDim.x * blockDim.x;
    float4 z = make_float4(0.f, 0.f, 0.f, 0.f);
    for (int i = blockIdx.x * blockDim.x + threadIdx.x; i < total; i += stride) {
        if (i < n * 16) ((float4*)g_agg_h)[i] = z;
        else            g_sum4[i - n * 16] = z;
    }
}

// ---------------------------------------------------------------------------
extern "C" void kernel_launch(void* const* d_in, const int* in_sizes, int n_in,
                              void* d_out, int out_size)
{
    const float* h     = (const float*)d_in[0];
    const float* coord = (const float*)d_in[1];
    const float* vel   = (const float*)d_in[2];
    const int*   eidx  = (const int*)d_in[4];
    const float* We1 = (const float*)d_in[5];
    const float* be1 = (const float*)d_in[6];
    const float* We2 = (const float*)d_in[7];
    const float* be2 = (const float*)d_in[8];
    const float* Wn1 = (const float*)d_in[9];
    const float* bn1 = (const float*)d_in[10];
    const float* Wn2 = (const float*)d_in[11];
    const float* bn2 = (const float*)d_in[12];
    const float* Wc1 = (const float*)d_in[13];
    const float* bc1 = (const float*)d_in[14];
    const float* Wc2 = (const float*)d_in[15];
    const float* bc2 = (const float*)d_in[16];

    const int N = in_sizes[0] / 64;
    const int E = in_sizes[4] / 2;

    float* out       = (float*)d_out;
    float* out_h     = out;
    float* out_coord = out + (size_t)N * 64;
    float* out_v     = out_coord + (size_t)N * 3;

    cudaFuncSetAttribute(edge_mma_kernel, cudaFuncAttributeMaxDynamicSharedMemorySize, SMEM_E);
    cudaFuncSetAttribute(node_mma_kernel, cudaFuncAttributeMaxDynamicSharedMemorySize, SMEM_N);

    zero_kernel<<<512, 256>>>(N);
    edge_mma_kernel<<<148, ETPB, SMEM_E>>>(h, coord, eidx, E,
                                           We1, be1, We2, be2, Wc1, bc1, Wc2, bc2);
    node_mma_kernel<<<148, 256, SMEM_N>>>(h, Wn1, bn1, Wn2, bn2,
                                          coord, vel, out_h, out_coord, out_v, N);
}

// round 6
// speedup vs baseline: 12.3368x; 1.0936x over previous
#include <cuda_runtime.h>
#include <cuda_bf16.h>
#include <cstdint>

typedef unsigned long long u64;
#define FULLM 0xffffffffu

#define NMAX 50048
__device__ float  g_agg_h[(size_t)NMAX * 64];
__device__ float4 g_sum4[NMAX];

// ===========================================================================
// common helpers
// ===========================================================================
__device__ __forceinline__ uint32_t smem_to_u32(const void* p) {
    uint32_t a;
    asm("{ .reg .u64 t; cvta.to.shared.u64 t, %1; cvt.u32.u64 %0, t; }" : "=r"(a) : "l"(p));
    return a;
}
__device__ __forceinline__ void ldsm4(uint32_t r[4], uint32_t addr) {
    asm volatile("ldmatrix.sync.aligned.m8n8.x4.shared.b16 {%0,%1,%2,%3}, [%4];"
        : "=r"(r[0]), "=r"(r[1]), "=r"(r[2]), "=r"(r[3]) : "r"(addr));
}
__device__ __forceinline__ void mma_bf16(float c[4], const uint32_t a[4],
                                         uint32_t b0, uint32_t b1) {
    asm volatile("mma.sync.aligned.m16n8k16.row.col.f32.bf16.bf16.f32 "
        "{%0,%1,%2,%3},{%4,%5,%6,%7},{%8,%9},{%0,%1,%2,%3};"
        : "+f"(c[0]), "+f"(c[1]), "+f"(c[2]), "+f"(c[3])
        : "r"(a[0]), "r"(a[1]), "r"(a[2]), "r"(a[3]), "r"(b0), "r"(b1));
}
__device__ __forceinline__ void packhl(float a, float b, uint32_t &hi, uint32_t &lo) {
    __nv_bfloat162 hh = __floats2bfloat162_rn(a, b);
    float ra = a - __bfloat162float(hh.x);
    float rb = b - __bfloat162float(hh.y);
    __nv_bfloat162 ll = __floats2bfloat162_rn(ra, rb);
    hi = *(uint32_t*)&hh;
    lo = *(uint32_t*)&ll;
}
__device__ __forceinline__ uint32_t packh(float a, float b) {
    __nv_bfloat162 hh = __floats2bfloat162_rn(a, b);
    return *(uint32_t*)&hh;
}
__device__ __forceinline__ void putw(char* sm, int plane, int j, int k, float x) {
    __nv_bfloat16 hb = __float2bfloat16(x);
    __nv_bfloat16 lb = __float2bfloat16(x - __bfloat162float(hb));
    uint32_t off = (uint32_t)(j * 128 + ((k * 2) ^ ((j & 7) << 4)));
    *(__nv_bfloat16*)(sm + plane + off) = hb;
    *(__nv_bfloat16*)(sm + plane + 8192 + off) = lb;
}

// ===========================================================================
// Edge kernel smem layout
// ===========================================================================
#define ETPB 320
#define EWARPS 10
#define W1A_HI   0
#define W1B_HI   16384
#define W2_HI    32768
#define WC_HI    49152
#define A_OFF    65536                       // per warp 8192 (hi|lo 4096)
#define MISC_OFF (A_OFF + EWARPS * 8192)     // fp32: be1|be2|bc1|wc2|w1rad
#define SMEM_E   (MISC_OFF + 1280)

__global__ __launch_bounds__(ETPB, 1) void edge_mma_kernel(
    const float* __restrict__ h, const float* __restrict__ coord,
    const int* __restrict__ eidx, int E,
    const float* __restrict__ We1, const float* __restrict__ be1,
    const float* __restrict__ We2, const float* __restrict__ be2,
    const float* __restrict__ Wc1, const float* __restrict__ bc1,
    const float* __restrict__ Wc2, const float* __restrict__ bc2)
{
    extern __shared__ char sm[];
    const uint32_t smb = smem_to_u32(sm);
    const int tid = threadIdx.x;
    float* sMisc = (float*)(sm + MISC_OFF);

    for (int i = tid; i < 129 * 64; i += ETPB) {
        int k = i >> 6, j = i & 63;
        float x = We1[i];
        if (k < 128) putw(sm, (k < 64) ? W1A_HI : W1B_HI, j, k & 63, x);
        else         sMisc[256 + j] = x;
    }
    for (int i = tid; i < 64 * 64; i += ETPB) {
        int k = i >> 6, j = i & 63;
        putw(sm, W2_HI, j, k, We2[i]);
        putw(sm, WC_HI, j, k, Wc1[i]);     // lo plane written but unused (1-term gate)
    }
    if (tid < 64)        sMisc[tid] = be1[tid];
    else if (tid < 128)  sMisc[tid] = be2[tid - 64];
    else if (tid < 192)  sMisc[tid] = bc1[tid - 128];
    else if (tid < 256)  sMisc[tid] = Wc2[tid - 192];
    const float bc2v = bc2[0];
    __syncthreads();

    const int warp = tid >> 5, lane = tid & 31;
    char* aPtr = sm + A_OFF + warp * 8192;
    const uint32_t aHi = smb + A_OFF + warp * 8192;

    const int aRowL = ((lane >> 3) & 1) * 8 + (lane & 7);
    const int aCbL  = ((lane >> 4) & 1) * 16;
    const int bRowL = ((lane >> 4) & 1) * 8 + (lane & 7);
    const int bCbL  = ((lane >> 3) & 1) * 16;
    const int q2 = (lane & 3) * 2;
    const int qr = lane >> 2;

    const int estride = gridDim.x * ETPB;

    for (int e0 = (blockIdx.x * EWARPS + warp) * 32; e0 < E; e0 += estride) {
        int e = e0 + lane;
        bool valid = e < E;
        int ec = valid ? e : (E - 1);
        int r = eidx[ec], cI = eidx[E + ec];
        float dx = coord[r * 3 + 0] - coord[cI * 3 + 0];
        float dy = coord[r * 3 + 1] - coord[cI * 3 + 1];
        float dz = coord[r * 3 + 2] - coord[cI * 3 + 2];
        float rad = valid ? (dx * dx + dy * dy + dz * dz) : 0.f;
        int rI = valid ? r : -1;

        float C[2][8][4];
        #pragma unroll
        for (int m = 0; m < 2; m++)
            #pragma unroll
            for (int n = 0; n < 8; n++)
                #pragma unroll
                for (int k = 0; k < 4; k++) C[m][n][k] = 0.f;

        // ================= GEMM1 =================
        #pragma unroll
        for (int half = 0; half < 2; half++) {
            __syncwarp();
            #pragma unroll
            for (int i = 0; i < 16; i++) {
                int edge = (i << 1) | (lane >> 4);
                int node = __shfl_sync(FULLM, half ? cI : r, edge);
                float4 v = *(const float4*)(h + (size_t)node * 64 + (lane & 15) * 4);
                uint32_t h0, l0, h1, l1;
                packhl(v.x, v.y, h0, l0);
                packhl(v.z, v.w, h1, l1);
                uint32_t off = (uint32_t)(edge * 128 + (((lane & 15) * 8) ^ ((edge & 7) << 4)));
                *(uint2*)(aPtr + off)        = make_uint2(h0, h1);
                *(uint2*)(aPtr + 4096 + off) = make_uint2(l0, l1);
            }
            __syncwarp();

            const uint32_t wB = smb + (half ? W1B_HI : W1A_HI);
            #pragma unroll
            for (int kt = 0; kt < 4; kt++) {
                uint32_t Ah[2][4], Al[2][4];
                #pragma unroll
                for (int m = 0; m < 2; m++) {
                    int ar = m * 16 + aRowL;
                    uint32_t ad = aHi + ar * 128 + ((kt * 32 + aCbL) ^ ((ar & 7) << 4));
                    ldsm4(Ah[m], ad);
                    ldsm4(Al[m], ad + 4096);
                }
                #pragma unroll
                for (int nt2 = 0; nt2 < 4; nt2++) {
                    uint32_t Bh[4], Bl[4];
                    int br = nt2 * 16 + bRowL;
                    uint32_t bd = wB + br * 128 + ((kt * 32 + bCbL) ^ ((br & 7) << 4));
                    ldsm4(Bh, bd);
                    ldsm4(Bl, bd + 8192);
                    #pragma unroll
                    for (int m = 0; m < 2; m++)
                        #pragma unroll
                        for (int p = 0; p < 2; p++) {
                            float* cc = C[m][nt2 * 2 + p];
                            mma_bf16(cc, Ah[m], Bh[2 * p], Bh[2 * p + 1]);
                            mma_bf16(cc, Ah[m], Bl[2 * p], Bl[2 * p + 1]);
                            mma_bf16(cc, Al[m], Bh[2 * p], Bh[2 * p + 1]);
                        }
                }
            }
        }

        // ---- epi1 ----
        uint32_t A2h[2][4][4], A2l[2][4][4];
        #pragma unroll
        for (int m = 0; m < 2; m++) {
            float rad0 = __shfl_sync(FULLM, rad, m * 16 + qr);
            float rad1 = __shfl_sync(FULLM, rad, m * 16 + 8 + qr);
            #pragma unroll
            for (int nt = 0; nt < 8; nt++) {
                int col0 = nt * 8 + q2;
                float2 bb = *(float2*)(sMisc + col0);
                float2 wr = *(float2*)(sMisc + 256 + col0);
                float c0 = fmaxf(C[m][nt][0] + bb.x + rad0 * wr.x, 0.f);
                float c1 = fmaxf(C[m][nt][1] + bb.y + rad0 * wr.y, 0.f);
                float c2 = fmaxf(C[m][nt][2] + bb.x + rad1 * wr.x, 0.f);
                float c3 = fmaxf(C[m][nt][3] + bb.y + rad1 * wr.y, 0.f);
                int kt = nt >> 1, o = (nt & 1) * 2;
                packhl(c0, c1, A2h[m][kt][o],     A2l[m][kt][o]);
                packhl(c2, c3, A2h[m][kt][o + 1], A2l[m][kt][o + 1]);
            }
        }

        // ================= GEMM2 =================
        float C2[2][8][4];
        #pragma unroll
        for (int m = 0; m < 2; m++)
            #pragma unroll
            for (int n = 0; n < 8; n++)
                #pragma unroll
                for (int k = 0; k < 4; k++) C2[m][n][k] = 0.f;
        #pragma unroll
        for (int kt = 0; kt < 4; kt++) {
            #pragma unroll
            for (int nt2 = 0; nt2 < 4; nt2++) {
                uint32_t Bh[4], Bl[4];
                int br = nt2 * 16 + bRowL;
                uint32_t bd = smb + W2_HI + br * 128 + ((kt * 32 + bCbL) ^ ((br & 7) << 4));
                ldsm4(Bh, bd);
                ldsm4(Bl, bd + 8192);
                #pragma unroll
                for (int m = 0; m < 2; m++)
                    #pragma unroll
                    for (int p = 0; p < 2; p++) {
                        float* cc = C2[m][nt2 * 2 + p];
                        mma_bf16(cc, A2h[m][kt], Bh[2 * p], Bh[2 * p + 1]);
                        mma_bf16(cc, A2h[m][kt], Bl[2 * p], Bl[2 * p + 1]);
                        mma_bf16(cc, A2l[m][kt], Bh[2 * p], Bh[2 * p + 1]);
                    }
            }
        }

        // ---- epi2: feat = relu(C2 + be2); float4 atomics via quad pairing ----
        uint32_t A3h[2][4][4];
        #pragma unroll
        for (int m = 0; m < 2; m++) {
            int rr0 = __shfl_sync(FULLM, rI, m * 16 + qr);
            int rr1 = __shfl_sync(FULLM, rI, m * 16 + 8 + qr);
            #pragma unroll
            for (int nt = 0; nt < 8; nt++) {
                int col0 = nt * 8 + q2;
                float2 bb = *(float2*)(sMisc + 64 + col0);
                float f0 = fmaxf(C2[m][nt][0] + bb.x, 0.f);
                float f1 = fmaxf(C2[m][nt][1] + bb.y, 0.f);
                float f2 = fmaxf(C2[m][nt][2] + bb.x, 0.f);
                float f3 = fmaxf(C2[m][nt][3] + bb.y, 0.f);
                int kt = nt >> 1, o = (nt & 1) * 2;
                A3h[m][kt][o]     = packh(f0, f1);
                A3h[m][kt][o + 1] = packh(f2, f3);
                // partner lane's col pair
                float g0 = __shfl_xor_sync(FULLM, f0, 1);
                float g1 = __shfl_xor_sync(FULLM, f1, 1);
                float g2 = __shfl_xor_sync(FULLM, f2, 1);
                float g3 = __shfl_xor_sync(FULLM, f3, 1);
                if ((lane & 1) == 0) {
                    int cb = nt * 8 + ((lane & 3) >> 1) * 4;
                    if (rr0 >= 0)
                        atomicAdd((float4*)(g_agg_h + (size_t)rr0 * 64 + cb),
                                  make_float4(f0, f1, g0, g1));
                    if (rr1 >= 0)
                        atomicAdd((float4*)(g_agg_h + (size_t)rr1 * 64 + cb),
                                  make_float4(f2, f3, g2, g3));
                }
            }
        }

        // ================= GEMM3 (gate, hi-only) =================
        float C3[2][8][4];
        #pragma unroll
        for (int m = 0; m < 2; m++)
            #pragma unroll
            for (int n = 0; n < 8; n++)
                #pragma unroll
                for (int k = 0; k < 4; k++) C3[m][n][k] = 0.f;
        #pragma unroll
        for (int kt = 0; kt < 4; kt++) {
            #pragma unroll
            for (int nt2 = 0; nt2 < 4; nt2++) {
                uint32_t Bh[4];
                int br = nt2 * 16 + bRowL;
                uint32_t bd = smb + WC_HI + br * 128 + ((kt * 32 + bCbL) ^ ((br & 7) << 4));
                ldsm4(Bh, bd);
                #pragma unroll
                for (int m = 0; m < 2; m++)
                    #pragma unroll
                    for (int p = 0; p < 2; p++)
                        mma_bf16(C3[m][nt2 * 2 + p], A3h[m][kt], Bh[2 * p], Bh[2 * p + 1]);
            }
        }

        // ---- epi3 ----
        #pragma unroll
        for (int m = 0; m < 2; m++) {
            float p0 = 0.f, p1 = 0.f;
            #pragma unroll
            for (int nt = 0; nt < 8; nt++) {
                int col0 = nt * 8 + q2;
                float2 bb = *(float2*)(sMisc + 128 + col0);
                float2 w2 = *(float2*)(sMisc + 192 + col0);
                p0 += fmaxf(C3[m][nt][0] + bb.x, 0.f) * w2.x
                    + fmaxf(C3[m][nt][1] + bb.y, 0.f) * w2.y;
                p1 += fmaxf(C3[m][nt][2] + bb.x, 0.f) * w2.x
                    + fmaxf(C3[m][nt][3] + bb.y, 0.f) * w2.y;
            }
            p0 += __shfl_xor_sync(FULLM, p0, 1);
            p0 += __shfl_xor_sync(FULLM, p0, 2);
            p1 += __shfl_xor_sync(FULLM, p1, 1);
            p1 += __shfl_xor_sync(FULLM, p1, 2);

            int row0 = m * 16 + qr, row1 = row0 + 8;
            float gx0 = __shfl_sync(FULLM, dx, row0), gy0 = __shfl_sync(FULLM, dy, row0),
                  gz0 = __shfl_sync(FULLM, dz, row0);
            float gx1 = __shfl_sync(FULLM, dx, row1), gy1 = __shfl_sync(FULLM, dy, row1),
                  gz1 = __shfl_sync(FULLM, dz, row1);
            int r0v = __shfl_sync(FULLM, rI, row0);
            int r1v = __shfl_sync(FULLM, rI, row1);

            if ((lane & 3) == 0) {
                if (r0v >= 0) {
                    float gt = p0 + bc2v;
                    atomicAdd(&g_sum4[r0v], make_float4(
                        fminf(fmaxf(gx0 * gt, -100.f), 100.f),
                        fminf(fmaxf(gy0 * gt, -100.f), 100.f),
                        fminf(fmaxf(gz0 * gt, -100.f), 100.f), 1.f));
                }
                if (r1v >= 0) {
                    float gt = p1 + bc2v;
                    atomicAdd(&g_sum4[r1v], make_float4(
                        fminf(fmaxf(gx1 * gt, -100.f), 100.f),
                        fminf(fmaxf(gy1 * gt, -100.f), 100.f),
                        fminf(fmaxf(gz1 * gt, -100.f), 100.f), 1.f));
                }
            }
        }
    }
}

// ===========================================================================
// Node kernel: bf16x3 HMMA, warp = 32 nodes x 64 outs; coord fused at head
// ===========================================================================
#define NW1A 0
#define NW1B 16384
#define NW2  32768
#define NMISC 49152
#define NA_OFF 50176
#define SMEM_N (NA_OFF + 8 * 8192)

__global__ __launch_bounds__(256, 1) void node_mma_kernel(
    const float* __restrict__ h,
    const float* __restrict__ Wn1, const float* __restrict__ bn1,
    const float* __restrict__ Wn2, const float* __restrict__ bn2,
    const float* __restrict__ coord, const float* __restrict__ vel,
    float* __restrict__ out_h, float* __restrict__ out_coord,
    float* __restrict__ out_v, int N)
{
    extern __shared__ char sm[];
    const uint32_t smb = smem_to_u32(sm);
    const int tid = threadIdx.x;
    float* sMisc = (float*)(sm + NMISC);

    for (int i = blockIdx.x * 256 + tid; i < N; i += gridDim.x * 256) {
        float4 s = g_sum4[i];
        float c = s.w;
        float invc = (c > 0.f) ? (1.f / fmaxf(c, 1.f)) : 0.f;
        float vx = vel[i * 3 + 0] + s.x * invc * 0.125f;
        float vy = vel[i * 3 + 1] + s.y * invc * 0.125f;
        float vz = vel[i * 3 + 2] + s.z * invc * 0.125f;
        out_v[i * 3 + 0] = vx;
        out_v[i * 3 + 1] = vy;
        out_v[i * 3 + 2] = vz;
        out_coord[i * 3 + 0] = coord[i * 3 + 0] + vx * 0.125f;
        out_coord[i * 3 + 1] = coord[i * 3 + 1] + vy * 0.125f;
        out_coord[i * 3 + 2] = coord[i * 3 + 2] + vz * 0.125f;
    }

    for (int i = tid; i < 128 * 64; i += 256) {
        int k = i >> 6, j = i & 63;
        putw(sm, (k < 64) ? NW1A : NW1B, j, k & 63, Wn1[i]);
    }
    for (int i = tid; i < 64 * 64; i += 256) {
        int k = i >> 6, j = i & 63;
        putw(sm, NW2, j, k, Wn2[i]);
    }
    if (tid < 64)        sMisc[tid] = bn1[tid];
    else if (tid < 128)  sMisc[tid] = bn2[tid - 64];
    __syncthreads();

    const int warp = tid >> 5, lane = tid & 31;
    char* aPtr = sm + NA_OFF + warp * 8192;
    const uint32_t aHi = smb + NA_OFF + warp * 8192;

    const int aRowL = ((lane >> 3) & 1) * 8 + (lane & 7);
    const int aCbL  = ((lane >> 4) & 1) * 16;
    const int bRowL = ((lane >> 4) & 1) * 8 + (lane & 7);
    const int bCbL  = ((lane >> 3) & 1) * 16;
    const int q2 = (lane & 3) * 2;
    const int qr = lane >> 2;

    const int ntiles = (N + 31) >> 5;

    for (int t = blockIdx.x * 8 + warp; t < ntiles; t += gridDim.x * 8) {
        const int nbase = t << 5;

        float C[2][8][4];
        #pragma unroll
        for (int m = 0; m < 2; m++)
            #pragma unroll
            for (int n = 0; n < 8; n++)
                #pragma unroll
                for (int k = 0; k < 4; k++) C[m][n][k] = 0.f;

        #pragma unroll
        for (int half = 0; half < 2; half++) {
            __syncwarp();
            const float* src = half ? g_agg_h : h;
            #pragma unroll
            for (int i = 0; i < 16; i++) {
                int row = (i << 1) | (lane >> 4);
                int node = nbase + row;
                if (node >= N) node = N - 1;
                float4 v = *(const float4*)(src + (size_t)node * 64 + (lane & 15) * 4);
                uint32_t h0, l0, h1, l1;
                packhl(v.x, v.y, h0, l0);
                packhl(v.z, v.w, h1, l1);
                uint32_t off = (uint32_t)(row * 128 + (((lane & 15) * 8) ^ ((row & 7) << 4)));
                *(uint2*)(aPtr + off)        = make_uint2(h0, h1);
                *(uint2*)(aPtr + 4096 + off) = make_uint2(l0, l1);
            }
            __syncwarp();

            const uint32_t wB = smb + (half ? NW1B : NW1A);
            #pragma unroll
            for (int kt = 0; kt < 4; kt++) {
                uint32_t Ah[2][4], Al[2][4];
                #pragma unroll
                for (int m = 0; m < 2; m++) {
                    int ar = m * 16 + aRowL;
                    uint32_t ad = aHi + ar * 128 + ((kt * 32 + aCbL) ^ ((ar & 7) << 4));
                    ldsm4(Ah[m], ad);
                    ldsm4(Al[m], ad + 4096);
                }
                #pragma unroll
                for (int nt2 = 0; nt2 < 4; nt2++) {
                    uint32_t Bh[4], Bl[4];
                    int br = nt2 * 16 + bRowL;
                    uint32_t bd = wB + br * 128 + ((kt * 32 + bCbL) ^ ((br & 7) << 4));
                    ldsm4(Bh, bd);
                    ldsm4(Bl, bd + 8192);
                    #pragma unroll
                    for (int m = 0; m < 2; m++)
                        #pragma unroll
                        for (int p = 0; p < 2; p++) {
                            float* cc = C[m][nt2 * 2 + p];
                            mma_bf16(cc, Ah[m], Bh[2 * p], Bh[2 * p + 1]);
                            mma_bf16(cc, Ah[m], Bl[2 * p], Bl[2 * p + 1]);
                            mma_bf16(cc, Al[m], Bh[2 * p], Bh[2 * p + 1]);
                        }
                }
            }
        }

        uint32_t A2h[2][4][4], A2l[2][4][4];
        #pragma unroll
        for (int m = 0; m < 2; m++) {
            #pragma unroll
            for (int nt = 0; nt < 8; nt++) {
                int col0 = nt * 8 + q2;
                float2 bb = *(float2*)(sMisc + col0);
                float c0 = fmaxf(C[m][nt][0] + bb.x, 0.f);
                float c1 = fmaxf(C[m][nt][1] + bb.y, 0.f);
                float c2 = fmaxf(C[m][nt][2] + bb.x, 0.f);
                float c3 = fmaxf(C[m][nt][3] + bb.y, 0.f);
                int kt = nt >> 1, o = (nt & 1) * 2;
                packhl(c0, c1, A2h[m][kt][o],     A2l[m][kt][o]);
                packhl(c2, c3, A2h[m][kt][o + 1], A2l[m][kt][o + 1]);
            }
        }

        float C2[2][8][4];
        #pragma unroll
        for (int m = 0; m < 2; m++)
            #pragma unroll
            for (int n = 0; n < 8; n++)
                #pragma unroll
                for (int k = 0; k < 4; k++) C2[m][n][k] = 0.f;
        #pragma unroll
        for (int kt = 0; kt < 4; kt++) {
            #pragma unroll
            for (int nt2 = 0; nt2 < 4; nt2++) {
                uint32_t Bh[4], Bl[4];
                int br = nt2 * 16 + bRowL;
                uint32_t bd = smb + NW2 + br * 128 + ((kt * 32 + bCbL) ^ ((br & 7) << 4));
                ldsm4(Bh, bd);
                ldsm4(Bl, bd + 8192);
                #pragma unroll
                for (int m = 0; m < 2; m++)
                    #pragma unroll
                    for (int p = 0; p < 2; p++) {
                        float* cc = C2[m][nt2 * 2 + p];
                        mma_bf16(cc, A2h[m][kt], Bh[2 * p], Bh[2 * p + 1]);
                        mma_bf16(cc, A2h[m][kt], Bl[2 * p], Bl[2 * p + 1]);
                        mma_bf16(cc, A2l[m][kt], Bh[2 * p], Bh[2 * p + 1]);
                    }
            }
        }

        #pragma unroll
        for (int m = 0; m < 2; m++) {
            int row0 = nbase + m * 16 + qr;
            int row1 = row0 + 8;
            bool v0 = row0 < N, v1 = row1 < N;
            #pragma unroll
            for (int nt = 0; nt < 8; nt++) {
                int col0 = nt * 8 + q2;
                float2 bb = *(float2*)(sMisc + 64 + col0);
                if (v0) {
                    float2 rs = *(const float2*)(h + (size_t)row0 * 64 + col0);
                    float2 o = make_float2(C2[m][nt][0] + bb.x + rs.x,
                                           C2[m][nt][1] + bb.y + rs.y);
                    *(float2*)(out_h + (size_t)row0 * 64 + col0) = o;
                }
                if (v1) {
                    float2 rs = *(const float2*)(h + (size_t)row1 * 64 + col0);
                    float2 o = make_float2(C2[m][nt][2] + bb.x + rs.x,
                                           C2[m][nt][3] + bb.y + rs.y);
                    *(float2*)(out_h + (size_t)row1 * 64 + col0) = o;
                }
            }
        }
    }
}

// ---------------------------------------------------------------------------
__global__ void zero_kernel(int n) {
    int total = n * 17;
    int stride = gridDim.x * blockDim.x;
    float4 z = make_float4(0.f, 0.f, 0.f, 0.f);
    for (int i = blockIdx.x * blockDim.x + threadIdx.x; i < total; i += stride) {
        if (i < n * 16) ((float4*)g_agg_h)[i] = z;
        else            g_sum4[i - n * 16] = z;
    }
}

// ---------------------------------------------------------------------------
extern "C" void kernel_launch(void* const* d_in, const int* in_sizes, int n_in,
                              void* d_out, int out_size)
{
    const float* h     = (const float*)d_in[0];
    const float* coord = (const float*)d_in[1];
    const float* vel   = (const float*)d_in[2];
    const int*   eidx  = (const int*)d_in[4];
    const float* We1 = (const float*)d_in[5];
    const float* be1 = (const float*)d_in[6];
    const float* We2 = (const float*)d_in[7];
    const float* be2 = (const float*)d_in[8];
    const float* Wn1 = (const float*)d_in[9];
    const float* bn1 = (const float*)d_in[10];
    const float* Wn2 = (const float*)d_in[11];
    const float* bn2 = (const float*)d_in[12];
    const float* Wc1 = (const float*)d_in[13];
    const float* bc1 = (const float*)d_in[14];
    const float* Wc2 = (const float*)d_in[15];
    const float* bc2 = (const float*)d_in[16];

    const int N = in_sizes[0] / 64;
    const int E = in_sizes[4] / 2;

    float* out       = (float*)d_out;
    float* out_h     = out;
    float* out_coord = out + (size_t)N * 64;
    float* out_v     = out_coord + (size_t)N * 3;

    cudaFuncSetAttribute(edge_mma_kernel, cudaFuncAttributeMaxDynamicSharedMemorySize, SMEM_E);
    cudaFuncSetAttribute(node_mma_kernel, cudaFuncAttributeMaxDynamicSharedMemorySize, SMEM_N);

    zero_kernel<<<512, 256>>>(N);
    edge_mma_kernel<<<148, ETPB, SMEM_E>>>(h, coord, eidx, E,
                                           We1, be1, We2, be2, Wc1, bc1, Wc2, bc2);
    node_mma_kernel<<<148, 256, SMEM_N>>>(h, Wn1, bn1, Wn2, bn2,
                                          coord, vel, out_h, out_coord, out_v, N);
}